// round 14
// baseline (speedup 1.0000x reference)
#include <cuda_runtime.h>
#include <cuda_bf16.h>
#include <cuda_fp16.h>
#include <cstdint>

// ---------------- problem constants ----------------
constexpr int T_  = 16;
constexpr int N_  = 50000;
constexpr int F_  = 128;
constexpr int B_  = 1024;
constexpr int S0_ = 10;
constexpr int S1_ = 5;
constexpr int H0_ = 128;
constexpr int H1_ = 64;
constexpr int C_  = 10;
constexpr int G_  = 8;
constexpr int K_  = 5;

constexpr int ROWS0 = B_ + B_ * S0_;   // 11264 rows per time step
constexpr int M0    = T_ * ROWS0;      // 180224
constexpr int M1    = T_ * B_;         // 16384
constexpr int KD    = 256;             // concat K dim [self | neigh]
constexpr int NTILES = M0 / 128;       // 1408
constexpr int TILE_BYTES = 131072;     // [ph0 hi 32K][ph0 lo 32K][ph1 hi 32K][ph1 lo 32K]

constexpr float FIX_MARGIN = 8e-5f;

// ---------------- device scratch ----------------
__device__ unsigned char g_spk0[(size_t)M0 * H0_];           // u8 0/1 spikes (23 MB)
__device__ __align__(16) char g_A0[(size_t)NTILES * TILE_BYTES]; // fp16 hi/lo swizzled A (184 MB)
__device__ float g_spk1[(size_t)M1 * H1_];
__device__ float g_W1[KD * H1_];
__device__ float g_M[T_ * H1_ * C_];
__device__ __align__(16) char g_W0img[2][32768];             // fp16 W hi per k-phase
__device__ float g_W0catT[H0_ * KD];                         // fp32 W, n-major (fixup)
__device__ float g_Ecol[H0_];                                // certified band per column

// ================= helpers =================
__device__ __forceinline__ uint32_t smem_u32(const void* p) {
    uint32_t a;
    asm("{ .reg .u64 t; cvta.to.shared.u64 t, %1; cvt.u32.u64 %0, t; }" : "=r"(a) : "l"(p));
    return a;
}
__device__ __forceinline__ void ldsm_x4(uint32_t* r, uint32_t addr) {
    asm volatile("ldmatrix.sync.aligned.m8n8.x4.shared.b16 {%0,%1,%2,%3}, [%4];"
        : "=r"(r[0]), "=r"(r[1]), "=r"(r[2]), "=r"(r[3]) : "r"(addr));
}
__device__ __forceinline__ void ldsm_x4_t(uint32_t* r, uint32_t addr) {
    asm volatile("ldmatrix.sync.aligned.m8n8.x4.trans.shared.b16 {%0,%1,%2,%3}, [%4];"
        : "=r"(r[0]), "=r"(r[1]), "=r"(r[2]), "=r"(r[3]) : "r"(addr));
}
__device__ __forceinline__ void mma16816(float* d, const uint32_t* a, const uint32_t* b) {
    asm volatile("mma.sync.aligned.m16n8k16.row.col.f32.f16.f16.f32 "
        "{%0,%1,%2,%3}, {%4,%5,%6,%7}, {%8,%9}, {%0,%1,%2,%3};"
        : "+f"(d[0]), "+f"(d[1]), "+f"(d[2]), "+f"(d[3])
        : "r"(a[0]), "r"(a[1]), "r"(a[2]), "r"(a[3]), "r"(b[0]), "r"(b[1]));
}
__device__ __forceinline__ void cp_async16(uint32_t smem_dst, const void* gmem_src) {
    asm volatile("cp.async.cg.shared.global [%0], [%1], 16;"
        :: "r"(smem_dst), "l"(gmem_src) : "memory");
}
#define CP_COMMIT() asm volatile("cp.async.commit_group;" ::: "memory")
#define CP_WAIT1()  asm volatile("cp.async.wait_group 1;" ::: "memory")

// W image: row = k (0..127), 128 n fp16 => 256B/row, XOR-swizzled 16B chunks
__device__ __forceinline__ uint32_t wimg_off(int k, int n) {
    uint32_t chunk = (uint32_t)(n >> 3) ^ (uint32_t)(k & 7);
    return (uint32_t)(k * 256 + (chunk << 4) + (n & 7) * 2);
}
// per-phase A tile: row (0..127), 128 k fp16 => 256B/row, XOR-swizzled 16B chunks
__device__ __forceinline__ uint32_t atile_off(int row, int kk) {
    uint32_t chunk = (uint32_t)(kk >> 3) ^ (uint32_t)(row & 7);
    return (uint32_t)(row * 256 + (chunk << 4) + (kk & 7) * 2);
}
__device__ __forceinline__ void hsplit2(float a, float b, uint32_t& hi, uint32_t& lo) {
    __half ah = __float2half_rn(a);
    __half bh = __float2half_rn(b);
    __half al = __float2half_rn(a - __half2float(ah));
    __half bl = __float2half_rn(b - __half2float(bh));
    hi = (uint32_t)__half_as_ushort(ah) | ((uint32_t)__half_as_ushort(bh) << 16);
    lo = (uint32_t)__half_as_ushort(al) | ((uint32_t)__half_as_ushort(bl) << 16);
}

// ---------------- prep ----------------
__global__ void prep_kernel(const float* __restrict__ dl, const float* __restrict__ dw,
                            const float* __restrict__ pw,
                            const float* __restrict__ Ws0, const float* __restrict__ Wn0,
                            const float* __restrict__ Ws1, const float* __restrict__ Wn1) {
    int tid = threadIdx.x;  // 256
    for (int i = tid; i < 256 * 128; i += 256) {
        int k = i >> 7, n = i & 127;
        float w = (k < 128) ? Ws0[k * H0_ + n] : Wn0[(k - 128) * H0_ + n];
        __half wh = __float2half_rn(w);
        int ph = k >> 7, kl = k & 127;
        *(__half*)(g_W0img[ph] + wimg_off(kl, n)) = wh;
        g_W0catT[n * KD + k] = w;
    }
    for (int i = tid; i < KD * H1_; i += 256) {
        int k = i / H1_, n = i % H1_;
        g_W1[i] = (k < H0_) ? Ws1[k * H1_ + n] : Wn1[(k - H0_) * H1_ + n];
    }
    __syncthreads();
    // certified per-column bound on dropped Ah*Wl product (A in [0,1))
    if (tid < H0_) {
        int n = tid;
        float e = 0.f;
        for (int k = 0; k < KD; k++) {
            float w = g_W0catT[n * KD + k];
            float wl = w - __half2float(__float2half_rn(w));
            e += fabsf(wl);
        }
        g_Ecol[n] = e + FIX_MARGIN;
    }
    if (tid < H1_) {
        int h = tid, g = h / (H1_ / G_);
        float l0 = dl[g * 3 + 0], l1 = dl[g * 3 + 1], l2 = dl[g * 3 + 2];
        float mx = fmaxf(l0, fmaxf(l1, l2));
        float e0 = expf(l0 - mx), e1 = expf(l1 - mx), e2 = expf(l2 - mx);
        float inv = 1.0f / (e0 + e1 + e2);
        float w[3] = {e0 * inv, e1 * inv, e2 * inv};
        float cw[T_];
        for (int u = 0; u < T_; u++) {
            float a = 0.f;
            for (int k = 0; k < K_; k++) {
                int t = u - k + 2;
                if (t >= 0 && t < T_) a += dw[h * K_ + k];
            }
            cw[u] = a;
        }
        const int D[3] = {1, 3, 5};
        for (int s = 0; s < T_; s++) {
            float coef = 0.f;
            for (int i2 = 0; i2 < 3; i2++) {
                int u = s + D[i2];
                if (u < T_) coef += w[i2] * cw[u];
            }
            for (int c = 0; c < C_; c++)
                g_M[(s * H1_ + h) * C_ + c] = coef * pw[h * C_ + c] * (1.0f / T_);
        }
    }
}

// ---------------- gather: warp-per-row, writes mma-ready fp16 hi/lo tiles ----------------
template <int S>
__device__ __forceinline__ float4 nbr_mean(const float* __restrict__ xt,
                                           const int* __restrict__ nb, int fo) {
    float4 nv = make_float4(0.f, 0.f, 0.f, 0.f);
#pragma unroll
    for (int s = 0; s < S; s++) {
        float4 v = *(const float4*)(xt + (size_t)nb[s] * F_ + fo);
        nv.x += v.x; nv.y += v.y; nv.z += v.z; nv.w += v.w;
    }
    const float invS = 1.0f / (float)S;
    nv.x *= invS; nv.y *= invS; nv.z *= invS; nv.w *= invS;
    return nv;
}

__global__ __launch_bounds__(256) void gather_kernel(
        const float* __restrict__ x, const int* __restrict__ nodes,
        const int* __restrict__ nbr1, const int* __restrict__ nbr2) {
    int wid = threadIdx.x >> 5, l = threadIdx.x & 31;
    int m = blockIdx.x * 8 + wid;          // global row
    int t = m / ROWS0, r = m % ROWS0;
    const float* xt = x + (size_t)t * N_ * F_;
    int fo = l * 4;

    int self;
    float4 nv;
    if (r < B_) {
        self = nodes[r];
        nv = nbr_mean<S0_>(xt, nbr1 + ((size_t)t * B_ + r) * S0_, fo);
    } else {
        int j = r - B_;
        self = nbr1[(size_t)t * B_ * S0_ + j];
        nv = nbr_mean<S1_>(xt, nbr2 + ((size_t)t * B_ * S0_ + j) * S1_, fo);
    }
    float4 sv = *(const float4*)(xt + (size_t)self * F_ + fo);

    char* base = g_A0 + (size_t)(m >> 7) * TILE_BYTES;
    uint32_t off = atile_off(m & 127, fo);
    uint32_t h0, l0, h1, l1;
    hsplit2(sv.x, sv.y, h0, l0);
    hsplit2(sv.z, sv.w, h1, l1);
    *(uint2*)(base + off)         = make_uint2(h0, h1);   // ph0 hi
    *(uint2*)(base + 32768 + off) = make_uint2(l0, l1);   // ph0 lo
    hsplit2(nv.x, nv.y, h0, l0);
    hsplit2(nv.z, nv.w, h1, l1);
    *(uint2*)(base + 65536 + off) = make_uint2(h0, h1);   // ph1 hi
    *(uint2*)(base + 98304 + off) = make_uint2(l0, l1);   // ph1 lo
}

// ---------------- persistent cp.async ring-2 GEMM0 (2-product) + spike + coop fixup ----------------
constexpr int OFF_A   = 0;        // 2 slots x 64KB (hi 32K + lo 32K each)
constexpr int OFF_W   = 131072;   // 2 phases x 32KB
constexpr int OFF_BIAS= 196608;   // 128 floats
constexpr int OFF_ECOL= 197120;   // 128 floats
constexpr int SMEM_SZ = 197632;

__global__ __launch_bounds__(256, 1)
void gemm0_kernel(const float* __restrict__ bias) {
    extern __shared__ __align__(1024) char sm[];
    uint32_t smb = smem_u32(sm);
    int tid = threadIdx.x;
    int wid = tid >> 5;
    int l   = tid & 31;

    float* s_bias = (float*)(sm + OFF_BIAS);
    float* s_ecol = (float*)(sm + OFF_ECOL);

    {
        const uint4* src = (const uint4*)g_W0img;
        uint4* dst = (uint4*)(sm + OFF_W);
        for (int i = tid; i < 4096; i += 256) dst[i] = src[i];
        if (tid < 128) { s_bias[tid] = bias[tid]; s_ecol[tid] = g_Ecol[tid]; }
    }

    int G = (int)gridDim.x;
    int ntl = (blockIdx.x < NTILES) ? ((NTILES - 1 - (int)blockIdx.x) / G + 1) : 0;
    int nchunks = 2 * ntl;

    auto chunk_src = [&](int j) -> const char* {
        int tile = (int)blockIdx.x + (j >> 1) * G;
        return g_A0 + (size_t)tile * TILE_BYTES + (size_t)(j & 1) * 65536;
    };
    auto issue_chunk = [&](int j) {
        const char* src = chunk_src(j) + tid * 16;
        uint32_t dst = smb + OFF_A + (uint32_t)(j & 1) * 65536 + tid * 16;
#pragma unroll
        for (int i = 0; i < 16; i++) cp_async16(dst + i * 4096, src + i * 4096);
    };
    for (int j = 0; j < 2; j++) {
        if (j < nchunks) issue_chunk(j);
        CP_COMMIT();
    }
    __syncthreads();

    int wm = wid & 3, wn = wid >> 2;
    int m0 = wm * 32;
    int nb0 = wn * 64;

    uint32_t a_rowb[2]; int a_sw[2];
#pragma unroll
    for (int mt = 0; mt < 2; mt++) {
        int r = m0 + mt * 16 + (l & 15);
        a_rowb[mt] = (uint32_t)(r * 256);
        a_sw[mt] = r & 7;
    }
    int a_cs = l >> 4;
    int b_rowoff = (l & 7) + (l & 8);
    int b_sw = l & 7;
    int b_cs = l >> 4;
    uint32_t b_rowb = (uint32_t)(b_rowoff * 256);

    float acc[2][8][4];

#pragma unroll 1
    for (int j = 0; j < nchunks; j++) {
        int ph = j & 1;
        int tile = (int)blockIdx.x + (j >> 1) * G;
        uint32_t aH = smb + OFF_A + (uint32_t)ph * 65536;
        uint32_t aL = aH + 32768;
        uint32_t wB = smb + OFF_W + (uint32_t)ph * 32768;

        CP_WAIT1();
        __syncthreads();

        if (ph == 0) {
#pragma unroll
            for (int a = 0; a < 2; a++)
#pragma unroll
                for (int b = 0; b < 8; b++)
#pragma unroll
                    for (int c = 0; c < 4; c++) acc[a][b][c] = 0.f;
        }

#pragma unroll
        for (int ks = 0; ks < 8; ks++) {
            int chunk0 = ks * 2 + a_cs;
            uint32_t ah[2][4], al[2][4];
#pragma unroll
            for (int mt = 0; mt < 2; mt++) {
                uint32_t offc = (uint32_t)((chunk0 ^ a_sw[mt]) << 4);
                ldsm_x4(ah[mt], aH + a_rowb[mt] + offc);
                ldsm_x4(al[mt], aL + a_rowb[mt] + offc);
            }
            uint32_t wrow = b_rowb + (uint32_t)(ks * 4096);
#pragma unroll
            for (int n2 = 0; n2 < 4; n2++) {
                int chunkb = (nb0 >> 3) + n2 * 2 + b_cs;
                uint32_t offb = (uint32_t)((chunkb ^ b_sw) << 4);
                uint32_t bh[4];
                ldsm_x4_t(bh, wB + wrow + offb);
#pragma unroll
                for (int mt = 0; mt < 2; mt++) {
                    mma16816(acc[mt][n2 * 2 + 0], ah[mt], bh + 0);
                    mma16816(acc[mt][n2 * 2 + 1], ah[mt], bh + 2);
                    mma16816(acc[mt][n2 * 2 + 0], al[mt], bh + 0);
                    mma16816(acc[mt][n2 * 2 + 1], al[mt], bh + 2);
                }
            }
        }

        if (ph == 1) {
            size_t mblk = (size_t)tile * 128;
            int r_in = l >> 2;
            int c2 = (l & 3) * 2;
            uint64_t flags = 0ull;
#pragma unroll
            for (int mt = 0; mt < 2; mt++) {
                size_t grow0 = mblk + m0 + mt * 16 + r_in;
#pragma unroll
                for (int nt = 0; nt < 8; nt++) {
                    int col = nb0 + nt * 8 + c2;
                    float bb0 = s_bias[col], bb1 = s_bias[col + 1];
                    float e0 = s_ecol[col], e1 = s_ecol[col + 1];
                    float v00 = acc[mt][nt][0] + bb0;
                    float v01 = acc[mt][nt][1] + bb1;
                    float v10 = acc[mt][nt][2] + bb0;
                    float v11 = acc[mt][nt][3] + bb1;
                    uint16_t u0 = (uint16_t)(((v00 >= 1.0f) ? 1u : 0u) | (((v01 >= 1.0f) ? 1u : 0u) << 8));
                    uint16_t u1 = (uint16_t)(((v10 >= 1.0f) ? 1u : 0u) | (((v11 >= 1.0f) ? 1u : 0u) << 8));
                    *(uint16_t*)(g_spk0 + grow0 * H0_ + col) = u0;
                    *(uint16_t*)(g_spk0 + (grow0 + 8) * H0_ + col) = u1;
                    int slotb = (mt * 8 + nt) * 4;
                    if (fabsf(v00 - 1.0f) < e0) flags |= 1ull << (slotb + 0);
                    if (fabsf(v01 - 1.0f) < e1) flags |= 1ull << (slotb + 1);
                    if (fabsf(v10 - 1.0f) < e0) flags |= 1ull << (slotb + 2);
                    if (fabsf(v11 - 1.0f) < e1) flags |= 1ull << (slotb + 3);
                }
            }
            uint32_t flo = (uint32_t)flags, fhi = (uint32_t)(flags >> 32);
            const char* abase = g_A0 + (size_t)tile * TILE_BYTES;
            int ph_l = l >> 4;
            int kl = (l & 15) * 8;
#pragma unroll 1
            for (int slot = 0; slot < 64; slot++) {
                uint32_t bit = (slot < 32) ? ((flo >> slot) & 1u) : ((fhi >> (slot - 32)) & 1u);
                uint32_t ball = __ballot_sync(0xFFFFFFFFu, bit);
                while (ball) {
                    int src = __ffs(ball) - 1;
                    ball &= ball - 1;
                    int mt = slot >> 5, nt = (slot >> 2) & 7, e = slot & 3;
                    int row = m0 + mt * 16 + (src >> 2) + ((e & 2) ? 8 : 0);
                    int col = nb0 + nt * 8 + (src & 3) * 2 + (e & 1);
                    const char* ab = abase + ph_l * 65536 + atile_off(row, kl);
                    uint4 hp = *(const uint4*)ab;
                    uint4 lp = *(const uint4*)(ab + 32768);
                    const float* wc = g_W0catT + col * KD + ph_l * 128 + kl;
                    float4 w0 = *(const float4*)(wc);
                    float4 w1 = *(const float4*)(wc + 4);
                    float s = 0.f;
                    __half2 h2, l2;
                    h2 = *(__half2*)&hp.x; l2 = *(__half2*)&lp.x;
                    s = fmaf(__half2float(h2.x) + __half2float(l2.x), w0.x, s);
                    s = fmaf(__half2float(h2.y) + __half2float(l2.y), w0.y, s);
                    h2 = *(__half2*)&hp.y; l2 = *(__half2*)&lp.y;
                    s = fmaf(__half2float(h2.x) + __half2float(l2.x), w0.z, s);
                    s = fmaf(__half2float(h2.y) + __half2float(l2.y), w0.w, s);
                    h2 = *(__half2*)&hp.z; l2 = *(__half2*)&lp.z;
                    s = fmaf(__half2float(h2.x) + __half2float(l2.x), w1.x, s);
                    s = fmaf(__half2float(h2.y) + __half2float(l2.y), w1.y, s);
                    h2 = *(__half2*)&hp.w; l2 = *(__half2*)&lp.w;
                    s = fmaf(__half2float(h2.x) + __half2float(l2.x), w1.z, s);
                    s = fmaf(__half2float(h2.y) + __half2float(l2.y), w1.w, s);
#pragma unroll
                    for (int off = 16; off > 0; off >>= 1)
                        s += __shfl_xor_sync(0xFFFFFFFFu, s, off);
                    if (l == 0) {
                        float v = s + s_bias[col];
                        g_spk0[(mblk + row) * H0_ + col] = (v >= 1.0f) ? 1 : 0;
                    }
                }
            }
        }

        __syncthreads();
        if (j + 2 < nchunks) issue_chunk(j + 2);
        CP_COMMIT();
    }
}

// ---------------- fused buildA1 + GEMM1 + spike ----------------
// Block = one t, 64 consecutive b. Builds u8 A1 tile (self | nbr-sum) in smem
// directly from g_spk0, then fp32 FFMA GEMM with scale applied at As fill
// (bit-identical to the previous buildA1 + gemm1 pair).
__global__ __launch_bounds__(256) void gemm1_fused_kernel(const float* __restrict__ bias) {
    constexpr int BM = 64, BK = 32, TM = 4, BN = 64, TN = 4;
    __shared__ unsigned char A1t[BM][KD];     // 16 KB
    __shared__ float As[BK][BM + 4];
    __shared__ float Bs[BK][BN];
    int tid = threadIdx.x;
    int tx = tid & 15, ty = tid >> 4;
    int t = (int)blockIdx.x >> 4;
    int bb0 = ((int)blockIdx.x & 15) * BM;
    size_t base = (size_t)t * ROWS0;

    // build A1 tile: thread -> row = tid>>2, quarter q = tid&3 (32 u8 each half)
    {
        int row = tid >> 2;
        int q = tid & 3;
        int bb = bb0 + row;
        // self: k = q*32 .. +31
        const uint4* sp = (const uint4*)(g_spk0 + (base + bb) * H0_ + q * 32);
        *(uint4*)(&A1t[row][q * 32])      = sp[0];
        *(uint4*)(&A1t[row][q * 32 + 16]) = sp[1];
        // neigh sum: k = 128 + q*32 .. +31 ; packed u32 adds (bytes <= 10, no carry)
        uint4 acc0 = make_uint4(0, 0, 0, 0), acc1 = make_uint4(0, 0, 0, 0);
#pragma unroll
        for (int s = 0; s < S0_; s++) {
            const uint4* np = (const uint4*)(g_spk0 + (base + B_ + (size_t)bb * S0_ + s) * H0_ + q * 32);
            uint4 v0 = np[0], v1 = np[1];
            acc0.x += v0.x; acc0.y += v0.y; acc0.z += v0.z; acc0.w += v0.w;
            acc1.x += v1.x; acc1.y += v1.y; acc1.z += v1.z; acc1.w += v1.w;
        }
        *(uint4*)(&A1t[row][128 + q * 32])      = acc0;
        *(uint4*)(&A1t[row][128 + q * 32 + 16]) = acc1;
    }
    __syncthreads();

    float acc[TM][TN];
#pragma unroll
    for (int i = 0; i < TM; i++)
#pragma unroll
        for (int j = 0; j < TN; j++) acc[i][j] = 0.f;
    int a_r = tid >> 2;
    int a_c = (tid & 3) * 8;
    int b_r = tid / 16, b_c = (tid % 16) * 4;
    for (int k0 = 0; k0 < KD; k0 += BK) {
        float scale = (k0 < H0_) ? 1.0f : (1.0f / S0_);
        uint2 raw = *(const uint2*)(&A1t[a_r][k0 + a_c]);
        const unsigned char* pb = (const unsigned char*)&raw;
#pragma unroll
        for (int i = 0; i < 8; i++) As[a_c + i][a_r] = scale * (float)pb[i];
#pragma unroll
        for (int p = 0; p < 2; p++) {
            int row = b_r + p * 16;
            *(float4*)(&Bs[row][b_c]) = *(const float4*)(g_W1 + (size_t)(k0 + row) * BN + b_c);
        }
        __syncthreads();
#pragma unroll
        for (int kk = 0; kk < BK; kk++) {
            float a[TM], b[TN];
#pragma unroll
            for (int i = 0; i < TM; i++) a[i] = As[kk][ty * TM + i];
#pragma unroll
            for (int j = 0; j < TN; j++) b[j] = Bs[kk][tx * TN + j];
#pragma unroll
            for (int i = 0; i < TM; i++)
#pragma unroll
                for (int j = 0; j < TN; j++) acc[i][j] = fmaf(a[i], b[j], acc[i][j]);
        }
        __syncthreads();
    }
    size_t mb = (size_t)blockIdx.x * BM;
#pragma unroll
    for (int i = 0; i < TM; i++) {
        size_t m = mb + ty * TM + i;
        float4 v;
        v.x = (acc[i][0] + bias[tx * TN + 0] >= 1.0f) ? 1.0f : 0.0f;
        v.y = (acc[i][1] + bias[tx * TN + 1] >= 1.0f) ? 1.0f : 0.0f;
        v.z = (acc[i][2] + bias[tx * TN + 2] >= 1.0f) ? 1.0f : 0.0f;
        v.w = (acc[i][3] + bias[tx * TN + 3] >= 1.0f) ? 1.0f : 0.0f;
        *(float4*)(g_spk1 + m * BN + tx * TN) = v;
    }
}

// ---------------- final contraction ----------------
__global__ void final_kernel(const float* __restrict__ tb, float* __restrict__ out) {
    __shared__ float red[H1_][C_];
    int b = blockIdx.x, h = threadIdx.x;
    float acc[C_];
#pragma unroll
    for (int c = 0; c < C_; c++) acc[c] = 0.f;
    for (int t = 0; t < T_; t++) {
        float s = g_spk1[((size_t)t * B_ + b) * H1_ + h];
        const float* m = g_M + (t * H1_ + h) * C_;
#pragma unroll
        for (int c = 0; c < C_; c++) acc[c] = fmaf(s, m[c], acc[c]);
    }
#pragma unroll
    for (int c = 0; c < C_; c++) red[h][c] = acc[c];
    __syncthreads();
    if (h < C_) {
        float s = tb[h];
        for (int r = 0; r < H1_; r++) s += red[r][h];
        out[b * C_ + h] = s;
    }
}

// ---------------- launch (serial R10 configuration) ----------------
extern "C" void kernel_launch(void* const* d_in, const int* in_sizes, int n_in,
                              void* d_out, int out_size) {
    const float* x    = (const float*)d_in[0];
    const int*   nodes= (const int*)d_in[1];
    const int*   nbr1 = (const int*)d_in[2];
    const int*   nbr2 = (const int*)d_in[3];
    const float* Ws0  = (const float*)d_in[4];
    const float* Wn0  = (const float*)d_in[5];
    const float* b0   = (const float*)d_in[6];
    const float* Ws1  = (const float*)d_in[7];
    const float* Wn1  = (const float*)d_in[8];
    const float* b1   = (const float*)d_in[9];
    const float* dl   = (const float*)d_in[10];
    const float* dw   = (const float*)d_in[11];
    const float* pw   = (const float*)d_in[12];
    const float* tb   = (const float*)d_in[13];
    float* out = (float*)d_out;

    static bool init_done = false;
    if (!init_done) {
        cudaFuncSetAttribute(gemm0_kernel,
                             cudaFuncAttributeMaxDynamicSharedMemorySize, SMEM_SZ);
        init_done = true;
    }

    prep_kernel<<<1, 256>>>(dl, dw, pw, Ws0, Wn0, Ws1, Wn1);
    gather_kernel<<<M0 / 8, 256>>>(x, nodes, nbr1, nbr2);
    gemm0_kernel<<<152, 256, SMEM_SZ>>>(b0);
    gemm1_fused_kernel<<<M1 / 64, 256>>>(b1);
    final_kernel<<<B_, 64>>>(tb, out);
}

// round 15
// speedup vs baseline: 1.3461x; 1.3461x over previous
#include <cuda_runtime.h>
#include <cuda_bf16.h>
#include <cuda_fp16.h>
#include <cstdint>

// ---------------- problem constants ----------------
constexpr int T_  = 16;
constexpr int N_  = 50000;
constexpr int F_  = 128;
constexpr int B_  = 1024;
constexpr int S0_ = 10;
constexpr int S1_ = 5;
constexpr int H0_ = 128;
constexpr int H1_ = 64;
constexpr int C_  = 10;
constexpr int G_  = 8;
constexpr int K_  = 5;

constexpr int ROWS0 = B_ + B_ * S0_;   // 11264 rows per time step
constexpr int M0    = T_ * ROWS0;      // 180224
constexpr int M1    = T_ * B_;         // 16384
constexpr int KD    = 256;             // concat K dim [self | neigh]
constexpr int NTILES = M0 / 128;       // 1408
constexpr int TILE_BYTES = 131072;     // per tile: [ph0 hi 32K][ph0 lo 32K][ph1 hi 32K][ph1 lo 32K]

constexpr float FIX_MARGIN = 8e-5f;

// ---------------- device scratch ----------------
__device__ __nv_bfloat16 g_spk0[(size_t)M0 * H0_];  // layer-0 spikes, bf16 0/1 (46 MB)
__device__ __align__(16) char g_A0[(size_t)NTILES * TILE_BYTES]; // fp16 hi/lo swizzled A (184 MB)
__device__ float g_A1[(size_t)M1 * KD];
__device__ float g_spk1[(size_t)M1 * H1_];
__device__ float g_W1[KD * H1_];
__device__ float g_M[T_ * H1_ * C_];
__device__ __align__(16) char g_W0img[2][32768];             // fp16 W hi per k-phase
__device__ float g_W0catT[H0_ * KD];                         // fp32 W, n-major (fixup)
__device__ float g_Ecol[H0_];                                // certified band per column

// ================= helpers =================
__device__ __forceinline__ uint32_t smem_u32(const void* p) {
    uint32_t a;
    asm("{ .reg .u64 t; cvta.to.shared.u64 t, %1; cvt.u32.u64 %0, t; }" : "=r"(a) : "l"(p));
    return a;
}
__device__ __forceinline__ void ldsm_x4(uint32_t* r, uint32_t addr) {
    asm volatile("ldmatrix.sync.aligned.m8n8.x4.shared.b16 {%0,%1,%2,%3}, [%4];"
        : "=r"(r[0]), "=r"(r[1]), "=r"(r[2]), "=r"(r[3]) : "r"(addr));
}
__device__ __forceinline__ void ldsm_x4_t(uint32_t* r, uint32_t addr) {
    asm volatile("ldmatrix.sync.aligned.m8n8.x4.trans.shared.b16 {%0,%1,%2,%3}, [%4];"
        : "=r"(r[0]), "=r"(r[1]), "=r"(r[2]), "=r"(r[3]) : "r"(addr));
}
__device__ __forceinline__ void mma16816(float* d, const uint32_t* a, const uint32_t* b) {
    asm volatile("mma.sync.aligned.m16n8k16.row.col.f32.f16.f16.f32 "
        "{%0,%1,%2,%3}, {%4,%5,%6,%7}, {%8,%9}, {%0,%1,%2,%3};"
        : "+f"(d[0]), "+f"(d[1]), "+f"(d[2]), "+f"(d[3])
        : "r"(a[0]), "r"(a[1]), "r"(a[2]), "r"(a[3]), "r"(b[0]), "r"(b[1]));
}
__device__ __forceinline__ void cp_async16(uint32_t smem_dst, const void* gmem_src) {
    asm volatile("cp.async.cg.shared.global [%0], [%1], 16;"
        :: "r"(smem_dst), "l"(gmem_src) : "memory");
}
#define CP_COMMIT() asm volatile("cp.async.commit_group;" ::: "memory")
#define CP_WAIT1()  asm volatile("cp.async.wait_group 1;" ::: "memory")

// W image: row = k (0..127), 128 n fp16 => 256B/row, XOR-swizzled 16B chunks
__device__ __forceinline__ uint32_t wimg_off(int k, int n) {
    uint32_t chunk = (uint32_t)(n >> 3) ^ (uint32_t)(k & 7);
    return (uint32_t)(k * 256 + (chunk << 4) + (n & 7) * 2);
}
// per-phase A tile: row (0..127), 128 k fp16 => 256B/row, XOR-swizzled 16B chunks
__device__ __forceinline__ uint32_t atile_off(int row, int kk) {
    uint32_t chunk = (uint32_t)(kk >> 3) ^ (uint32_t)(row & 7);
    return (uint32_t)(row * 256 + (chunk << 4) + (kk & 7) * 2);
}
__device__ __forceinline__ void hsplit2(float a, float b, uint32_t& hi, uint32_t& lo) {
    __half ah = __float2half_rn(a);
    __half bh = __float2half_rn(b);
    __half al = __float2half_rn(a - __half2float(ah));
    __half bl = __float2half_rn(b - __half2float(bh));
    hi = (uint32_t)__half_as_ushort(ah) | ((uint32_t)__half_as_ushort(bh) << 16);
    lo = (uint32_t)__half_as_ushort(al) | ((uint32_t)__half_as_ushort(bl) << 16);
}

// ---------------- prep ----------------
__global__ void prep_kernel(const float* __restrict__ dl, const float* __restrict__ dw,
                            const float* __restrict__ pw,
                            const float* __restrict__ Ws0, const float* __restrict__ Wn0,
                            const float* __restrict__ Ws1, const float* __restrict__ Wn1) {
    int tid = threadIdx.x;  // 256
    for (int i = tid; i < 256 * 128; i += 256) {
        int k = i >> 7, n = i & 127;
        float w = (k < 128) ? Ws0[k * H0_ + n] : Wn0[(k - 128) * H0_ + n];
        __half wh = __float2half_rn(w);
        int ph = k >> 7, kl = k & 127;
        *(__half*)(g_W0img[ph] + wimg_off(kl, n)) = wh;
        g_W0catT[n * KD + k] = w;
    }
    for (int i = tid; i < KD * H1_; i += 256) {
        int k = i / H1_, n = i % H1_;
        g_W1[i] = (k < H0_) ? Ws1[k * H1_ + n] : Wn1[(k - H0_) * H1_ + n];
    }
    __syncthreads();
    // certified per-column bound on dropped Ah*Wl product (A in [0,1))
    if (tid < H0_) {
        int n = tid;
        float e = 0.f;
        for (int k = 0; k < KD; k++) {
            float w = g_W0catT[n * KD + k];
            float wl = w - __half2float(__float2half_rn(w));
            e += fabsf(wl);
        }
        g_Ecol[n] = e + FIX_MARGIN;
    }
    if (tid < H1_) {
        int h = tid, g = h / (H1_ / G_);
        float l0 = dl[g * 3 + 0], l1 = dl[g * 3 + 1], l2 = dl[g * 3 + 2];
        float mx = fmaxf(l0, fmaxf(l1, l2));
        float e0 = expf(l0 - mx), e1 = expf(l1 - mx), e2 = expf(l2 - mx);
        float inv = 1.0f / (e0 + e1 + e2);
        float w[3] = {e0 * inv, e1 * inv, e2 * inv};
        float cw[T_];
        for (int u = 0; u < T_; u++) {
            float a = 0.f;
            for (int k = 0; k < K_; k++) {
                int t = u - k + 2;
                if (t >= 0 && t < T_) a += dw[h * K_ + k];
            }
            cw[u] = a;
        }
        const int D[3] = {1, 3, 5};
        for (int s = 0; s < T_; s++) {
            float coef = 0.f;
            for (int i2 = 0; i2 < 3; i2++) {
                int u = s + D[i2];
                if (u < T_) coef += w[i2] * cw[u];
            }
            for (int c = 0; c < C_; c++)
                g_M[(s * H1_ + h) * C_ + c] = coef * pw[h * C_ + c] * (1.0f / T_);
        }
    }
}

// ---------------- gather: warp-per-row, writes mma-ready fp16 hi/lo tiles ----------------
template <int S>
__device__ __forceinline__ float4 nbr_mean(const float* __restrict__ xt,
                                           const int* __restrict__ nb, int fo) {
    float4 nv = make_float4(0.f, 0.f, 0.f, 0.f);
#pragma unroll
    for (int s = 0; s < S; s++) {
        float4 v = *(const float4*)(xt + (size_t)nb[s] * F_ + fo);
        nv.x += v.x; nv.y += v.y; nv.z += v.z; nv.w += v.w;
    }
    const float invS = 1.0f / (float)S;
    nv.x *= invS; nv.y *= invS; nv.z *= invS; nv.w *= invS;
    return nv;
}

__global__ __launch_bounds__(256) void gather_kernel(
        const float* __restrict__ x, const int* __restrict__ nodes,
        const int* __restrict__ nbr1, const int* __restrict__ nbr2) {
    int wid = threadIdx.x >> 5, l = threadIdx.x & 31;
    int m = blockIdx.x * 8 + wid;          // global row
    int t = m / ROWS0, r = m % ROWS0;
    const float* xt = x + (size_t)t * N_ * F_;
    int fo = l * 4;

    int self;
    float4 nv;
    if (r < B_) {
        self = nodes[r];
        nv = nbr_mean<S0_>(xt, nbr1 + ((size_t)t * B_ + r) * S0_, fo);
    } else {
        int j = r - B_;
        self = nbr1[(size_t)t * B_ * S0_ + j];
        nv = nbr_mean<S1_>(xt, nbr2 + ((size_t)t * B_ * S0_ + j) * S1_, fo);
    }
    float4 sv = *(const float4*)(xt + (size_t)self * F_ + fo);

    char* base = g_A0 + (size_t)(m >> 7) * TILE_BYTES;
    uint32_t off = atile_off(m & 127, fo);
    uint32_t h0, l0, h1, l1;
    hsplit2(sv.x, sv.y, h0, l0);
    hsplit2(sv.z, sv.w, h1, l1);
    *(uint2*)(base + off)         = make_uint2(h0, h1);   // ph0 hi
    *(uint2*)(base + 32768 + off) = make_uint2(l0, l1);   // ph0 lo
    hsplit2(nv.x, nv.y, h0, l0);
    hsplit2(nv.z, nv.w, h1, l1);
    *(uint2*)(base + 65536 + off) = make_uint2(h0, h1);   // ph1 hi
    *(uint2*)(base + 98304 + off) = make_uint2(l0, l1);   // ph1 lo
}

// ---------------- persistent cp.async ring-2 GEMM0 + spike + coop fixup ----------------
constexpr int OFF_A   = 0;        // 2 slots x 64KB (hi 32K + lo 32K each)
constexpr int OFF_W   = 131072;   // 2 phases x 32KB
constexpr int OFF_BIAS= 196608;   // 128 floats
constexpr int OFF_ECOL= 197120;   // 128 floats
constexpr int SMEM_SZ = 197632;

__global__ __launch_bounds__(256, 1)
void gemm0_kernel(const float* __restrict__ bias) {
    extern __shared__ __align__(1024) char sm[];
    uint32_t smb = smem_u32(sm);
    int tid = threadIdx.x;
    int wid = tid >> 5;
    int l   = tid & 31;

    float* s_bias = (float*)(sm + OFF_BIAS);
    float* s_ecol = (float*)(sm + OFF_ECOL);

    // W images (both phases) + bias/ecol
    {
        const uint4* src = (const uint4*)g_W0img;
        uint4* dst = (uint4*)(sm + OFF_W);
        for (int i = tid; i < 4096; i += 256) dst[i] = src[i];
        if (tid < 128) { s_bias[tid] = bias[tid]; s_ecol[tid] = g_Ecol[tid]; }
    }

    int G = (int)gridDim.x;
    int ntl = (blockIdx.x < NTILES) ? ((NTILES - 1 - (int)blockIdx.x) / G + 1) : 0;
    int nchunks = 2 * ntl;

    // chunk j -> tile blockIdx.x + (j>>1)*G, phase j&1, slot j&1
    auto chunk_src = [&](int j) -> const char* {
        int tile = (int)blockIdx.x + (j >> 1) * G;
        return g_A0 + (size_t)tile * TILE_BYTES + (size_t)(j & 1) * 65536;
    };
    // prologue: issue chunks 0 and 1
    for (int j = 0; j < 2; j++) {
        if (j < nchunks) {
            const char* src = chunk_src(j) + tid * 16;
            uint32_t dst = smb + OFF_A + (uint32_t)(j & 1) * 65536 + tid * 16;
#pragma unroll
            for (int i = 0; i < 16; i++) cp_async16(dst + i * 4096, src + i * 4096);
        }
        CP_COMMIT();
    }
    __syncthreads();   // W/bias visible before first mma

    // warp tiling: 4 warps M x 2 warps N; warp = 32 rows x 64 cols
    int wm = wid & 3, wn = wid >> 2;
    int m0 = wm * 32;
    int nb0 = wn * 64;

    uint32_t a_rowb[2]; int a_sw[2];
#pragma unroll
    for (int mt = 0; mt < 2; mt++) {
        int r = m0 + mt * 16 + (l & 15);
        a_rowb[mt] = (uint32_t)(r * 256);
        a_sw[mt] = r & 7;
    }
    int a_cs = l >> 4;
    int b_rowoff = (l & 7) + (l & 8);
    int b_sw = l & 7;
    int b_cs = l >> 4;
    uint32_t b_rowb = (uint32_t)(b_rowoff * 256);

    float acc[2][8][4];

#pragma unroll 1
    for (int j = 0; j < nchunks; j++) {
        int ph = j & 1;
        int tile = (int)blockIdx.x + (j >> 1) * G;
        uint32_t aH = smb + OFF_A + (uint32_t)ph * 65536;
        uint32_t aL = aH + 32768;
        uint32_t wB = smb + OFF_W + (uint32_t)ph * 32768;

        CP_WAIT1();          // chunk j arrived (thread-local)
        __syncthreads();     // visible to all

        if (ph == 0) {
#pragma unroll
            for (int a = 0; a < 2; a++)
#pragma unroll
                for (int b = 0; b < 8; b++)
#pragma unroll
                    for (int c = 0; c < 4; c++) acc[a][b][c] = 0.f;
        }

#pragma unroll
        for (int ks = 0; ks < 8; ks++) {
            int chunk0 = ks * 2 + a_cs;
            uint32_t ah[2][4], al[2][4];
#pragma unroll
            for (int mt = 0; mt < 2; mt++) {
                uint32_t offc = (uint32_t)((chunk0 ^ a_sw[mt]) << 4);
                ldsm_x4(ah[mt], aH + a_rowb[mt] + offc);
                ldsm_x4(al[mt], aL + a_rowb[mt] + offc);
            }
            uint32_t wrow = b_rowb + (uint32_t)(ks * 4096);
#pragma unroll
            for (int n2 = 0; n2 < 4; n2++) {
                int chunkb = (nb0 >> 3) + n2 * 2 + b_cs;
                uint32_t offb = (uint32_t)((chunkb ^ b_sw) << 4);
                uint32_t bh[4];
                ldsm_x4_t(bh, wB + wrow + offb);
#pragma unroll
                for (int mt = 0; mt < 2; mt++) {
                    mma16816(acc[mt][n2 * 2 + 0], ah[mt], bh + 0);
                    mma16816(acc[mt][n2 * 2 + 1], ah[mt], bh + 2);
                    mma16816(acc[mt][n2 * 2 + 0], al[mt], bh + 0);
                    mma16816(acc[mt][n2 * 2 + 1], al[mt], bh + 2);
                }
            }
        }

        if (ph == 1) {
            // ---- epilogue: +bias, threshold, flag borderline, write bf16 0/1 ----
            size_t mblk = (size_t)tile * 128;
            int r_in = l >> 2;
            int c2 = (l & 3) * 2;
            const uint32_t ONE = 0x3F80u;
            uint64_t flags = 0ull;
#pragma unroll
            for (int mt = 0; mt < 2; mt++) {
                size_t grow0 = mblk + m0 + mt * 16 + r_in;
#pragma unroll
                for (int nt = 0; nt < 8; nt++) {
                    int col = nb0 + nt * 8 + c2;
                    float bb0 = s_bias[col], bb1 = s_bias[col + 1];
                    float e0 = s_ecol[col], e1 = s_ecol[col + 1];
                    float v00 = acc[mt][nt][0] + bb0;
                    float v01 = acc[mt][nt][1] + bb1;
                    float v10 = acc[mt][nt][2] + bb0;
                    float v11 = acc[mt][nt][3] + bb1;
                    uint32_t u0 = ((v00 >= 1.0f) ? ONE : 0u) | (((v01 >= 1.0f) ? ONE : 0u) << 16);
                    uint32_t u1 = ((v10 >= 1.0f) ? ONE : 0u) | (((v11 >= 1.0f) ? ONE : 0u) << 16);
                    *(uint32_t*)((char*)g_spk0 + (grow0 * H0_ + col) * 2) = u0;
                    *(uint32_t*)((char*)g_spk0 + ((grow0 + 8) * H0_ + col) * 2) = u1;
                    int slotb = (mt * 8 + nt) * 4;
                    if (fabsf(v00 - 1.0f) < e0) flags |= 1ull << (slotb + 0);
                    if (fabsf(v01 - 1.0f) < e1) flags |= 1ull << (slotb + 1);
                    if (fabsf(v10 - 1.0f) < e0) flags |= 1ull << (slotb + 2);
                    if (fabsf(v11 - 1.0f) < e1) flags |= 1ull << (slotb + 3);
                }
            }
            // ---- warp-coop certified fixup: fp32 recompute from g_A0 hi+lo (L2-hot) ----
            uint32_t flo = (uint32_t)flags, fhi = (uint32_t)(flags >> 32);
            const char* abase = g_A0 + (size_t)tile * TILE_BYTES;
            int ph_l = l >> 4;             // lane's k-phase
            int kl = (l & 15) * 8;         // lane's k within phase (8 k's)
#pragma unroll 1
            for (int slot = 0; slot < 64; slot++) {
                uint32_t bit = (slot < 32) ? ((flo >> slot) & 1u) : ((fhi >> (slot - 32)) & 1u);
                uint32_t ball = __ballot_sync(0xFFFFFFFFu, bit);
                while (ball) {
                    int src = __ffs(ball) - 1;
                    ball &= ball - 1;
                    int mt = slot >> 5, nt = (slot >> 2) & 7, e = slot & 3;
                    int row = m0 + mt * 16 + (src >> 2) + ((e & 2) ? 8 : 0);
                    int col = nb0 + nt * 8 + (src & 3) * 2 + (e & 1);
                    const char* ab = abase + ph_l * 65536 + atile_off(row, kl);
                    uint4 hp = *(const uint4*)ab;
                    uint4 lp = *(const uint4*)(ab + 32768);
                    const float* wc = g_W0catT + col * KD + ph_l * 128 + kl;
                    float4 w0 = *(const float4*)(wc);
                    float4 w1 = *(const float4*)(wc + 4);
                    float s = 0.f;
                    __half2 h2, l2;
                    h2 = *(__half2*)&hp.x; l2 = *(__half2*)&lp.x;
                    s = fmaf(__half2float(h2.x) + __half2float(l2.x), w0.x, s);
                    s = fmaf(__half2float(h2.y) + __half2float(l2.y), w0.y, s);
                    h2 = *(__half2*)&hp.y; l2 = *(__half2*)&lp.y;
                    s = fmaf(__half2float(h2.x) + __half2float(l2.x), w0.z, s);
                    s = fmaf(__half2float(h2.y) + __half2float(l2.y), w0.w, s);
                    h2 = *(__half2*)&hp.z; l2 = *(__half2*)&lp.z;
                    s = fmaf(__half2float(h2.x) + __half2float(l2.x), w1.x, s);
                    s = fmaf(__half2float(h2.y) + __half2float(l2.y), w1.y, s);
                    h2 = *(__half2*)&hp.w; l2 = *(__half2*)&lp.w;
                    s = fmaf(__half2float(h2.x) + __half2float(l2.x), w1.z, s);
                    s = fmaf(__half2float(h2.y) + __half2float(l2.y), w1.w, s);
#pragma unroll
                    for (int off = 16; off > 0; off >>= 1)
                        s += __shfl_xor_sync(0xFFFFFFFFu, s, off);
                    if (l == 0) {
                        float v = s + s_bias[col];
                        g_spk0[(mblk + row) * H0_ + col] =
                            (v >= 1.0f) ? __ushort_as_bfloat16((unsigned short)0x3F80u)
                                        : __ushort_as_bfloat16((unsigned short)0);
                    }
                }
            }
        }

        __syncthreads();   // all warps done reading slot before overwrite
        if (j + 2 < nchunks) {
            const char* src = chunk_src(j + 2) + tid * 16;
            uint32_t dst = smb + OFF_A + (uint32_t)(j & 1) * 65536 + tid * 16;
#pragma unroll
            for (int i = 0; i < 16; i++) cp_async16(dst + i * 4096, src + i * 4096);
        }
        CP_COMMIT();       // unconditional: uniform pending-group count
    }
}

// ---------------- A1 = [spk_self | mean_{S0}(spk_nb)] ----------------
__global__ void buildA1_kernel() {
    int gid = blockIdx.x;
    int t = gid / B_, b = gid % B_;
    int h = threadIdx.x;
    size_t base = (size_t)t * ROWS0;
    float s_self = __bfloat162float(g_spk0[(base + b) * H0_ + h]);
    float acc = 0.f;
#pragma unroll
    for (int s = 0; s < S0_; s++)
        acc += __bfloat162float(g_spk0[(base + B_ + (size_t)b * S0_ + s) * H0_ + h]);
    float* dst = g_A1 + (size_t)gid * KD;
    dst[h] = s_self;
    dst[H0_ + h] = acc * (1.0f / S0_);
}

// ---------------- fp32 FFMA GEMM1 + spike ----------------
__global__ __launch_bounds__(256) void gemm1_kernel(const float* __restrict__ bias) {
    constexpr int BM = 128, BK = 32, TM = 8, BN = 64, TN = 4;
    __shared__ float As[BK][BM + 4];
    __shared__ float Bs[BK][BN];
    int tid = threadIdx.x;
    int tx = tid & 15, ty = tid >> 4;
    size_t mb = (size_t)blockIdx.x * BM;
    float acc[TM][TN];
#pragma unroll
    for (int i = 0; i < TM; i++)
#pragma unroll
        for (int j = 0; j < TN; j++) acc[i][j] = 0.f;
    int a_r = tid >> 3, a_c = (tid & 7) << 2;
    int b_r = tid / 16, b_c = (tid % 16) * 4;
    for (int k0 = 0; k0 < KD; k0 += BK) {
#pragma unroll
        for (int p = 0; p < 4; p++) {
            int row = a_r + p * 32;
            float4 v = *(const float4*)(g_A1 + (mb + row) * KD + k0 + a_c);
            As[a_c + 0][row] = v.x; As[a_c + 1][row] = v.y;
            As[a_c + 2][row] = v.z; As[a_c + 3][row] = v.w;
        }
#pragma unroll
        for (int p = 0; p < 2; p++) {
            int row = b_r + p * 16;
            *(float4*)(&Bs[row][b_c]) = *(const float4*)(g_W1 + (size_t)(k0 + row) * BN + b_c);
        }
        __syncthreads();
#pragma unroll
        for (int kk = 0; kk < BK; kk++) {
            float a[TM], b[TN];
#pragma unroll
            for (int i = 0; i < TM; i++) a[i] = As[kk][ty * TM + i];
#pragma unroll
            for (int j = 0; j < TN; j++) b[j] = Bs[kk][tx * TN + j];
#pragma unroll
            for (int i = 0; i < TM; i++)
#pragma unroll
                for (int j = 0; j < TN; j++) acc[i][j] = fmaf(a[i], b[j], acc[i][j]);
        }
        __syncthreads();
    }
#pragma unroll
    for (int i = 0; i < TM; i++) {
        size_t m = mb + ty * TM + i;
        float4 v;
        v.x = (acc[i][0] + bias[tx * TN + 0] >= 1.0f) ? 1.0f : 0.0f;
        v.y = (acc[i][1] + bias[tx * TN + 1] >= 1.0f) ? 1.0f : 0.0f;
        v.z = (acc[i][2] + bias[tx * TN + 2] >= 1.0f) ? 1.0f : 0.0f;
        v.w = (acc[i][3] + bias[tx * TN + 3] >= 1.0f) ? 1.0f : 0.0f;
        *(float4*)(g_spk1 + m * BN + tx * TN) = v;
    }
}

// ---------------- final contraction ----------------
__global__ void final_kernel(const float* __restrict__ tb, float* __restrict__ out) {
    __shared__ float red[H1_][C_];
    int b = blockIdx.x, h = threadIdx.x;
    float acc[C_];
#pragma unroll
    for (int c = 0; c < C_; c++) acc[c] = 0.f;
    for (int t = 0; t < T_; t++) {
        float s = g_spk1[((size_t)t * B_ + b) * H1_ + h];
        const float* m = g_M + (t * H1_ + h) * C_;
#pragma unroll
        for (int c = 0; c < C_; c++) acc[c] = fmaf(s, m[c], acc[c]);
    }
#pragma unroll
    for (int c = 0; c < C_; c++) red[h][c] = acc[c];
    __syncthreads();
    if (h < C_) {
        float s = tb[h];
        for (int r = 0; r < H1_; r++) s += red[r][h];
        out[b * C_ + h] = s;
    }
}

// ---------------- launch ----------------
extern "C" void kernel_launch(void* const* d_in, const int* in_sizes, int n_in,
                              void* d_out, int out_size) {
    const float* x    = (const float*)d_in[0];
    const int*   nodes= (const int*)d_in[1];
    const int*   nbr1 = (const int*)d_in[2];
    const int*   nbr2 = (const int*)d_in[3];
    const float* Ws0  = (const float*)d_in[4];
    const float* Wn0  = (const float*)d_in[5];
    const float* b0   = (const float*)d_in[6];
    const float* Ws1  = (const float*)d_in[7];
    const float* Wn1  = (const float*)d_in[8];
    const float* b1   = (const float*)d_in[9];
    const float* dl   = (const float*)d_in[10];
    const float* dw   = (const float*)d_in[11];
    const float* pw   = (const float*)d_in[12];
    const float* tb   = (const float*)d_in[13];
    float* out = (float*)d_out;

    static bool init_done = false;
    if (!init_done) {
        cudaFuncSetAttribute(gemm0_kernel,
                             cudaFuncAttributeMaxDynamicSharedMemorySize, SMEM_SZ);
        init_done = true;
    }

    prep_kernel<<<1, 256>>>(dl, dw, pw, Ws0, Wn0, Ws1, Wn1);
    gather_kernel<<<M0 / 8, 256>>>(x, nodes, nbr1, nbr2);
    gemm0_kernel<<<152, 256, SMEM_SZ>>>(b0);
    buildA1_kernel<<<M1, 128>>>();
    gemm1_kernel<<<M1 / 128, 256>>>(b1);
    final_kernel<<<B_, 64>>>(tb, out);
}

// round 16
// speedup vs baseline: 1.4769x; 1.0972x over previous
#include <cuda_runtime.h>
#include <cuda_bf16.h>
#include <cuda_fp16.h>
#include <cstdint>

// ---------------- problem constants ----------------
constexpr int T_  = 16;
constexpr int N_  = 50000;
constexpr int F_  = 128;
constexpr int B_  = 1024;
constexpr int S0_ = 10;
constexpr int S1_ = 5;
constexpr int H0_ = 128;
constexpr int H1_ = 64;
constexpr int C_  = 10;
constexpr int G_  = 8;
constexpr int K_  = 5;

constexpr int ROWS0 = B_ + B_ * S0_;   // 11264 rows per time step
constexpr int M0    = T_ * ROWS0;      // 180224
constexpr int M1    = T_ * B_;         // 16384
constexpr int KD    = 256;             // concat K dim [self | neigh]
constexpr int NTILES = M0 / 128;       // 1408
constexpr int TILE_BYTES = 131072;     // per tile: [ph0 hi 32K][ph0 lo 32K][ph1 hi 32K][ph1 lo 32K]

constexpr float FIX_MARGIN = 8e-5f;

// ---------------- device scratch ----------------
__device__ __nv_bfloat16 g_spk0[(size_t)M0 * H0_];  // layer-0 spikes, bf16 0/1 (46 MB)
__device__ __align__(16) char g_A0[(size_t)NTILES * TILE_BYTES]; // fp16 hi/lo swizzled A (184 MB)
__device__ float g_A1[(size_t)M1 * KD];
__device__ float g_spk1[(size_t)M1 * H1_];
__device__ float g_W1[KD * H1_];
__device__ float g_M[T_ * H1_ * C_];
__device__ __align__(16) char g_W0img[2][32768];             // fp16 W hi per k-phase
__device__ float g_W0catT[H0_ * KD];                         // fp32 W, n-major (fixup)
__device__ float g_Ecol[H0_];                                // certified band per column

// ================= helpers =================
__device__ __forceinline__ uint32_t smem_u32(const void* p) {
    uint32_t a;
    asm("{ .reg .u64 t; cvta.to.shared.u64 t, %1; cvt.u32.u64 %0, t; }" : "=r"(a) : "l"(p));
    return a;
}
__device__ __forceinline__ void ldsm_x4(uint32_t* r, uint32_t addr) {
    asm volatile("ldmatrix.sync.aligned.m8n8.x4.shared.b16 {%0,%1,%2,%3}, [%4];"
        : "=r"(r[0]), "=r"(r[1]), "=r"(r[2]), "=r"(r[3]) : "r"(addr));
}
__device__ __forceinline__ void ldsm_x4_t(uint32_t* r, uint32_t addr) {
    asm volatile("ldmatrix.sync.aligned.m8n8.x4.trans.shared.b16 {%0,%1,%2,%3}, [%4];"
        : "=r"(r[0]), "=r"(r[1]), "=r"(r[2]), "=r"(r[3]) : "r"(addr));
}
__device__ __forceinline__ void mma16816(float* d, const uint32_t* a, const uint32_t* b) {
    asm volatile("mma.sync.aligned.m16n8k16.row.col.f32.f16.f16.f32 "
        "{%0,%1,%2,%3}, {%4,%5,%6,%7}, {%8,%9}, {%0,%1,%2,%3};"
        : "+f"(d[0]), "+f"(d[1]), "+f"(d[2]), "+f"(d[3])
        : "r"(a[0]), "r"(a[1]), "r"(a[2]), "r"(a[3]), "r"(b[0]), "r"(b[1]));
}
__device__ __forceinline__ void cp_async16(uint32_t smem_dst, const void* gmem_src) {
    asm volatile("cp.async.cg.shared.global [%0], [%1], 16;"
        :: "r"(smem_dst), "l"(gmem_src) : "memory");
}
#define CP_COMMIT() asm volatile("cp.async.commit_group;" ::: "memory")
#define CP_WAIT1()  asm volatile("cp.async.wait_group 1;" ::: "memory")

// W image: row = k (0..127), 128 n fp16 => 256B/row, XOR-swizzled 16B chunks
__device__ __forceinline__ uint32_t wimg_off(int k, int n) {
    uint32_t chunk = (uint32_t)(n >> 3) ^ (uint32_t)(k & 7);
    return (uint32_t)(k * 256 + (chunk << 4) + (n & 7) * 2);
}
// per-phase A tile: row (0..127), 128 k fp16 => 256B/row, XOR-swizzled 16B chunks
__device__ __forceinline__ uint32_t atile_off(int row, int kk) {
    uint32_t chunk = (uint32_t)(kk >> 3) ^ (uint32_t)(row & 7);
    return (uint32_t)(row * 256 + (chunk << 4) + (kk & 7) * 2);
}
__device__ __forceinline__ void hsplit2(float a, float b, uint32_t& hi, uint32_t& lo) {
    __half ah = __float2half_rn(a);
    __half bh = __float2half_rn(b);
    __half al = __float2half_rn(a - __half2float(ah));
    __half bl = __float2half_rn(b - __half2float(bh));
    hi = (uint32_t)__half_as_ushort(ah) | ((uint32_t)__half_as_ushort(bh) << 16);
    lo = (uint32_t)__half_as_ushort(al) | ((uint32_t)__half_as_ushort(bl) << 16);
}

// ---------------- prep ----------------
__global__ void prep_kernel(const float* __restrict__ dl, const float* __restrict__ dw,
                            const float* __restrict__ pw,
                            const float* __restrict__ Ws0, const float* __restrict__ Wn0,
                            const float* __restrict__ Ws1, const float* __restrict__ Wn1) {
    int tid = threadIdx.x;  // 256
    for (int i = tid; i < 256 * 128; i += 256) {
        int k = i >> 7, n = i & 127;
        float w = (k < 128) ? Ws0[k * H0_ + n] : Wn0[(k - 128) * H0_ + n];
        __half wh = __float2half_rn(w);
        int ph = k >> 7, kl = k & 127;
        *(__half*)(g_W0img[ph] + wimg_off(kl, n)) = wh;
        g_W0catT[n * KD + k] = w;
    }
    for (int i = tid; i < KD * H1_; i += 256) {
        int k = i / H1_, n = i % H1_;
        g_W1[i] = (k < H0_) ? Ws1[k * H1_ + n] : Wn1[(k - H0_) * H1_ + n];
    }
    __syncthreads();
    // certified per-column bound on dropped Ah*Wl product (A in [0,1))
    if (tid < H0_) {
        int n = tid;
        float e = 0.f;
        for (int k = 0; k < KD; k++) {
            float w = g_W0catT[n * KD + k];
            float wl = w - __half2float(__float2half_rn(w));
            e += fabsf(wl);
        }
        g_Ecol[n] = e + FIX_MARGIN;
    }
    if (tid < H1_) {
        int h = tid, g = h / (H1_ / G_);
        float l0 = dl[g * 3 + 0], l1 = dl[g * 3 + 1], l2 = dl[g * 3 + 2];
        float mx = fmaxf(l0, fmaxf(l1, l2));
        float e0 = expf(l0 - mx), e1 = expf(l1 - mx), e2 = expf(l2 - mx);
        float inv = 1.0f / (e0 + e1 + e2);
        float w[3] = {e0 * inv, e1 * inv, e2 * inv};
        float cw[T_];
        for (int u = 0; u < T_; u++) {
            float a = 0.f;
            for (int k = 0; k < K_; k++) {
                int t = u - k + 2;
                if (t >= 0 && t < T_) a += dw[h * K_ + k];
            }
            cw[u] = a;
        }
        const int D[3] = {1, 3, 5};
        for (int s = 0; s < T_; s++) {
            float coef = 0.f;
            for (int i2 = 0; i2 < 3; i2++) {
                int u = s + D[i2];
                if (u < T_) coef += w[i2] * cw[u];
            }
            for (int c = 0; c < C_; c++)
                g_M[(s * H1_ + h) * C_ + c] = coef * pw[h * C_ + c] * (1.0f / T_);
        }
    }
}

// ---------------- gather: warp-per-row, writes mma-ready fp16 hi/lo tiles ----------------
template <int S>
__device__ __forceinline__ float4 nbr_mean(const float* __restrict__ xt,
                                           const int* __restrict__ nb, int fo) {
    float4 nv = make_float4(0.f, 0.f, 0.f, 0.f);
#pragma unroll
    for (int s = 0; s < S; s++) {
        float4 v = *(const float4*)(xt + (size_t)nb[s] * F_ + fo);
        nv.x += v.x; nv.y += v.y; nv.z += v.z; nv.w += v.w;
    }
    const float invS = 1.0f / (float)S;
    nv.x *= invS; nv.y *= invS; nv.z *= invS; nv.w *= invS;
    return nv;
}

__global__ __launch_bounds__(256) void gather_kernel(
        const float* __restrict__ x, const int* __restrict__ nodes,
        const int* __restrict__ nbr1, const int* __restrict__ nbr2) {
    int wid = threadIdx.x >> 5, l = threadIdx.x & 31;
    int m = blockIdx.x * 8 + wid;          // global row
    int t = m / ROWS0, r = m % ROWS0;
    const float* xt = x + (size_t)t * N_ * F_;
    int fo = l * 4;

    int self;
    float4 nv;
    if (r < B_) {
        self = nodes[r];
        nv = nbr_mean<S0_>(xt, nbr1 + ((size_t)t * B_ + r) * S0_, fo);
    } else {
        int j = r - B_;
        self = nbr1[(size_t)t * B_ * S0_ + j];
        nv = nbr_mean<S1_>(xt, nbr2 + ((size_t)t * B_ * S0_ + j) * S1_, fo);
    }
    float4 sv = *(const float4*)(xt + (size_t)self * F_ + fo);

    char* base = g_A0 + (size_t)(m >> 7) * TILE_BYTES;
    uint32_t off = atile_off(m & 127, fo);
    uint32_t h0, l0, h1, l1;
    hsplit2(sv.x, sv.y, h0, l0);
    hsplit2(sv.z, sv.w, h1, l1);
    *(uint2*)(base + off)         = make_uint2(h0, h1);   // ph0 hi
    *(uint2*)(base + 32768 + off) = make_uint2(l0, l1);   // ph0 lo
    hsplit2(nv.x, nv.y, h0, l0);
    hsplit2(nv.z, nv.w, h1, l1);
    *(uint2*)(base + 65536 + off) = make_uint2(h0, h1);   // ph1 hi
    *(uint2*)(base + 98304 + off) = make_uint2(l0, l1);   // ph1 lo
}

// ---------------- persistent cp.async ring-2 GEMM0, 512 threads ----------------
constexpr int OFF_A   = 0;        // 2 slots x 64KB (hi 32K + lo 32K each)
constexpr int OFF_W   = 131072;   // 2 phases x 32KB
constexpr int OFF_BIAS= 196608;   // 128 floats
constexpr int OFF_ECOL= 197120;   // 128 floats
constexpr int SMEM_SZ = 197632;

__global__ __launch_bounds__(512, 1)
void gemm0_kernel(const float* __restrict__ bias) {
    extern __shared__ __align__(1024) char sm[];
    uint32_t smb = smem_u32(sm);
    int tid = threadIdx.x;
    int wid = tid >> 5;          // 0..15
    int l   = tid & 31;

    float* s_bias = (float*)(sm + OFF_BIAS);
    float* s_ecol = (float*)(sm + OFF_ECOL);

    // W images (both phases) + bias/ecol
    {
        const uint4* src = (const uint4*)g_W0img;
        uint4* dst = (uint4*)(sm + OFF_W);
        for (int i = tid; i < 4096; i += 512) dst[i] = src[i];
        if (tid < 128) { s_bias[tid] = bias[tid]; s_ecol[tid] = g_Ecol[tid]; }
    }

    int G = (int)gridDim.x;
    int ntl = (blockIdx.x < NTILES) ? ((NTILES - 1 - (int)blockIdx.x) / G + 1) : 0;
    int nchunks = 2 * ntl;

    // chunk j -> tile blockIdx.x + (j>>1)*G, phase j&1, slot j&1 (64KB hi+lo)
    auto chunk_src = [&](int j) -> const char* {
        int tile = (int)blockIdx.x + (j >> 1) * G;
        return g_A0 + (size_t)tile * TILE_BYTES + (size_t)(j & 1) * 65536;
    };
    auto issue_chunk = [&](int j) {
        const char* src = chunk_src(j) + tid * 16;
        uint32_t dst = smb + OFF_A + (uint32_t)(j & 1) * 65536 + tid * 16;
#pragma unroll
        for (int i = 0; i < 8; i++) cp_async16(dst + i * 8192, src + i * 8192);
    };
    for (int j = 0; j < 2; j++) {
        if (j < nchunks) issue_chunk(j);
        CP_COMMIT();
    }
    __syncthreads();   // W/bias visible before first mma

    // warp tiling: 4 warps M x 4 warps N; warp = 32 rows x 32 cols
    int wm = wid & 3, wn = wid >> 2;
    int m0 = wm * 32;
    int nb0 = wn * 32;

    uint32_t a_rowb[2]; int a_sw[2];
#pragma unroll
    for (int mt = 0; mt < 2; mt++) {
        int r = m0 + mt * 16 + (l & 15);
        a_rowb[mt] = (uint32_t)(r * 256);
        a_sw[mt] = r & 7;
    }
    int a_cs = l >> 4;
    int b_rowoff = (l & 7) + (l & 8);
    int b_sw = l & 7;
    int b_cs = l >> 4;
    uint32_t b_rowb = (uint32_t)(b_rowoff * 256);

    float acc[2][4][4];

#pragma unroll 1
    for (int j = 0; j < nchunks; j++) {
        int ph = j & 1;
        int tile = (int)blockIdx.x + (j >> 1) * G;
        uint32_t aH = smb + OFF_A + (uint32_t)ph * 65536;
        uint32_t aL = aH + 32768;
        uint32_t wB = smb + OFF_W + (uint32_t)ph * 32768;

        CP_WAIT1();          // chunk j arrived (thread-local)
        __syncthreads();     // visible to all

        if (ph == 0) {
#pragma unroll
            for (int a = 0; a < 2; a++)
#pragma unroll
                for (int b = 0; b < 4; b++)
#pragma unroll
                    for (int c = 0; c < 4; c++) acc[a][b][c] = 0.f;
        }

#pragma unroll
        for (int ks = 0; ks < 8; ks++) {
            int chunk0 = ks * 2 + a_cs;
            uint32_t ah[2][4], al[2][4];
#pragma unroll
            for (int mt = 0; mt < 2; mt++) {
                uint32_t offc = (uint32_t)((chunk0 ^ a_sw[mt]) << 4);
                ldsm_x4(ah[mt], aH + a_rowb[mt] + offc);
                ldsm_x4(al[mt], aL + a_rowb[mt] + offc);
            }
            uint32_t wrow = b_rowb + (uint32_t)(ks * 4096);
#pragma unroll
            for (int n2 = 0; n2 < 2; n2++) {
                int chunkb = (nb0 >> 3) + n2 * 2 + b_cs;
                uint32_t offb = (uint32_t)((chunkb ^ b_sw) << 4);
                uint32_t bh[4];
                ldsm_x4_t(bh, wB + wrow + offb);
#pragma unroll
                for (int mt = 0; mt < 2; mt++) {
                    mma16816(acc[mt][n2 * 2 + 0], ah[mt], bh + 0);
                    mma16816(acc[mt][n2 * 2 + 1], ah[mt], bh + 2);
                    mma16816(acc[mt][n2 * 2 + 0], al[mt], bh + 0);
                    mma16816(acc[mt][n2 * 2 + 1], al[mt], bh + 2);
                }
            }
        }

        if (ph == 1) {
            // ---- epilogue: +bias, threshold, flag borderline, write bf16 0/1 ----
            size_t mblk = (size_t)tile * 128;
            int r_in = l >> 2;
            int c2 = (l & 3) * 2;
            const uint32_t ONE = 0x3F80u;
            uint32_t flags = 0u;
#pragma unroll
            for (int mt = 0; mt < 2; mt++) {
                size_t grow0 = mblk + m0 + mt * 16 + r_in;
#pragma unroll
                for (int nt = 0; nt < 4; nt++) {
                    int col = nb0 + nt * 8 + c2;
                    float bb0 = s_bias[col], bb1 = s_bias[col + 1];
                    float e0 = s_ecol[col], e1 = s_ecol[col + 1];
                    float v00 = acc[mt][nt][0] + bb0;
                    float v01 = acc[mt][nt][1] + bb1;
                    float v10 = acc[mt][nt][2] + bb0;
                    float v11 = acc[mt][nt][3] + bb1;
                    uint32_t u0 = ((v00 >= 1.0f) ? ONE : 0u) | (((v01 >= 1.0f) ? ONE : 0u) << 16);
                    uint32_t u1 = ((v10 >= 1.0f) ? ONE : 0u) | (((v11 >= 1.0f) ? ONE : 0u) << 16);
                    *(uint32_t*)((char*)g_spk0 + (grow0 * H0_ + col) * 2) = u0;
                    *(uint32_t*)((char*)g_spk0 + ((grow0 + 8) * H0_ + col) * 2) = u1;
                    int slotb = (mt * 4 + nt) * 4;
                    if (fabsf(v00 - 1.0f) < e0) flags |= 1u << (slotb + 0);
                    if (fabsf(v01 - 1.0f) < e1) flags |= 1u << (slotb + 1);
                    if (fabsf(v10 - 1.0f) < e0) flags |= 1u << (slotb + 2);
                    if (fabsf(v11 - 1.0f) < e1) flags |= 1u << (slotb + 3);
                }
            }
            // ---- warp-coop certified fixup: fp32 recompute from g_A0 hi+lo (L2-hot) ----
            const char* abase = g_A0 + (size_t)tile * TILE_BYTES;
            int ph_l = l >> 4;             // lane's k-phase
            int kl = (l & 15) * 8;         // lane's k within phase (8 k's)
#pragma unroll 1
            for (int slot = 0; slot < 32; slot++) {
                uint32_t bit = (flags >> slot) & 1u;
                uint32_t ball = __ballot_sync(0xFFFFFFFFu, bit);
                while (ball) {
                    int src = __ffs(ball) - 1;
                    ball &= ball - 1;
                    int mt = slot >> 4, nt = (slot >> 2) & 3, e = slot & 3;
                    int row = m0 + mt * 16 + (src >> 2) + ((e & 2) ? 8 : 0);
                    int col = nb0 + nt * 8 + (src & 3) * 2 + (e & 1);
                    const char* ab = abase + ph_l * 65536 + atile_off(row, kl);
                    uint4 hp = *(const uint4*)ab;
                    uint4 lp = *(const uint4*)(ab + 32768);
                    const float* wc = g_W0catT + col * KD + ph_l * 128 + kl;
                    float4 w0 = *(const float4*)(wc);
                    float4 w1 = *(const float4*)(wc + 4);
                    float s = 0.f;
                    __half2 h2, l2;
                    h2 = *(__half2*)&hp.x; l2 = *(__half2*)&lp.x;
                    s = fmaf(__half2float(h2.x) + __half2float(l2.x), w0.x, s);
                    s = fmaf(__half2float(h2.y) + __half2float(l2.y), w0.y, s);
                    h2 = *(__half2*)&hp.y; l2 = *(__half2*)&lp.y;
                    s = fmaf(__half2float(h2.x) + __half2float(l2.x), w0.z, s);
                    s = fmaf(__half2float(h2.y) + __half2float(l2.y), w0.w, s);
                    h2 = *(__half2*)&hp.z; l2 = *(__half2*)&lp.z;
                    s = fmaf(__half2float(h2.x) + __half2float(l2.x), w1.x, s);
                    s = fmaf(__half2float(h2.y) + __half2float(l2.y), w1.y, s);
                    h2 = *(__half2*)&hp.w; l2 = *(__half2*)&lp.w;
                    s = fmaf(__half2float(h2.x) + __half2float(l2.x), w1.z, s);
                    s = fmaf(__half2float(h2.y) + __half2float(l2.y), w1.w, s);
#pragma unroll
                    for (int off = 16; off > 0; off >>= 1)
                        s += __shfl_xor_sync(0xFFFFFFFFu, s, off);
                    if (l == 0) {
                        float v = s + s_bias[col];
                        g_spk0[(mblk + row) * H0_ + col] =
                            (v >= 1.0f) ? __ushort_as_bfloat16((unsigned short)0x3F80u)
                                        : __ushort_as_bfloat16((unsigned short)0);
                    }
                }
            }
        }

        __syncthreads();   // all warps done reading slot before overwrite
        if (j + 2 < nchunks) issue_chunk(j + 2);
        CP_COMMIT();       // unconditional: uniform pending-group count
    }
}

// ---------------- A1 = [spk_self | mean_{S0}(spk_nb)] ----------------
__global__ void buildA1_kernel() {
    int gid = blockIdx.x;
    int t = gid / B_, b = gid % B_;
    int h = threadIdx.x;
    size_t base = (size_t)t * ROWS0;
    float s_self = __bfloat162float(g_spk0[(base + b) * H0_ + h]);
    float acc = 0.f;
#pragma unroll
    for (int s = 0; s < S0_; s++)
        acc += __bfloat162float(g_spk0[(base + B_ + (size_t)b * S0_ + s) * H0_ + h]);
    float* dst = g_A1 + (size_t)gid * KD;
    dst[h] = s_self;
    dst[H0_ + h] = acc * (1.0f / S0_);
}

// ---------------- fp32 FFMA GEMM1 + spike ----------------
__global__ __launch_bounds__(256) void gemm1_kernel(const float* __restrict__ bias) {
    constexpr int BM = 128, BK = 32, TM = 8, BN = 64, TN = 4;
    __shared__ float As[BK][BM + 4];
    __shared__ float Bs[BK][BN];
    int tid = threadIdx.x;
    int tx = tid & 15, ty = tid >> 4;
    size_t mb = (size_t)blockIdx.x * BM;
    float acc[TM][TN];
#pragma unroll
    for (int i = 0; i < TM; i++)
#pragma unroll
        for (int j = 0; j < TN; j++) acc[i][j] = 0.f;
    int a_r = tid >> 3, a_c = (tid & 7) << 2;
    int b_r = tid / 16, b_c = (tid % 16) * 4;
    for (int k0 = 0; k0 < KD; k0 += BK) {
#pragma unroll
        for (int p = 0; p < 4; p++) {
            int row = a_r + p * 32;
            float4 v = *(const float4*)(g_A1 + (mb + row) * KD + k0 + a_c);
            As[a_c + 0][row] = v.x; As[a_c + 1][row] = v.y;
            As[a_c + 2][row] = v.z; As[a_c + 3][row] = v.w;
        }
#pragma unroll
        for (int p = 0; p < 2; p++) {
            int row = b_r + p * 16;
            *(float4*)(&Bs[row][b_c]) = *(const float4*)(g_W1 + (size_t)(k0 + row) * BN + b_c);
        }
        __syncthreads();
#pragma unroll
        for (int kk = 0; kk < BK; kk++) {
            float a[TM], b[TN];
#pragma unroll
            for (int i = 0; i < TM; i++) a[i] = As[kk][ty * TM + i];
#pragma unroll
            for (int j = 0; j < TN; j++) b[j] = Bs[kk][tx * TN + j];
#pragma unroll
            for (int i = 0; i < TM; i++)
#pragma unroll
                for (int j = 0; j < TN; j++) acc[i][j] = fmaf(a[i], b[j], acc[i][j]);
        }
        __syncthreads();
    }
#pragma unroll
    for (int i = 0; i < TM; i++) {
        size_t m = mb + ty * TM + i;
        float4 v;
        v.x = (acc[i][0] + bias[tx * TN + 0] >= 1.0f) ? 1.0f : 0.0f;
        v.y = (acc[i][1] + bias[tx * TN + 1] >= 1.0f) ? 1.0f : 0.0f;
        v.z = (acc[i][2] + bias[tx * TN + 2] >= 1.0f) ? 1.0f : 0.0f;
        v.w = (acc[i][3] + bias[tx * TN + 3] >= 1.0f) ? 1.0f : 0.0f;
        *(float4*)(g_spk1 + m * BN + tx * TN) = v;
    }
}

// ---------------- final contraction ----------------
__global__ void final_kernel(const float* __restrict__ tb, float* __restrict__ out) {
    __shared__ float red[H1_][C_];
    int b = blockIdx.x, h = threadIdx.x;
    float acc[C_];
#pragma unroll
    for (int c = 0; c < C_; c++) acc[c] = 0.f;
    for (int t = 0; t < T_; t++) {
        float s = g_spk1[((size_t)t * B_ + b) * H1_ + h];
        const float* m = g_M + (t * H1_ + h) * C_;
#pragma unroll
        for (int c = 0; c < C_; c++) acc[c] = fmaf(s, m[c], acc[c]);
    }
#pragma unroll
    for (int c = 0; c < C_; c++) red[h][c] = acc[c];
    __syncthreads();
    if (h < C_) {
        float s = tb[h];
        for (int r = 0; r < H1_; r++) s += red[r][h];
        out[b * C_ + h] = s;
    }
}

// ---------------- launch ----------------
extern "C" void kernel_launch(void* const* d_in, const int* in_sizes, int n_in,
                              void* d_out, int out_size) {
    const float* x    = (const float*)d_in[0];
    const int*   nodes= (const int*)d_in[1];
    const int*   nbr1 = (const int*)d_in[2];
    const int*   nbr2 = (const int*)d_in[3];
    const float* Ws0  = (const float*)d_in[4];
    const float* Wn0  = (const float*)d_in[5];
    const float* b0   = (const float*)d_in[6];
    const float* Ws1  = (const float*)d_in[7];
    const float* Wn1  = (const float*)d_in[8];
    const float* b1   = (const float*)d_in[9];
    const float* dl   = (const float*)d_in[10];
    const float* dw   = (const float*)d_in[11];
    const float* pw   = (const float*)d_in[12];
    const float* tb   = (const float*)d_in[13];
    float* out = (float*)d_out;

    static bool init_done = false;
    if (!init_done) {
        cudaFuncSetAttribute(gemm0_kernel,
                             cudaFuncAttributeMaxDynamicSharedMemorySize, SMEM_SZ);
        init_done = true;
    }

    prep_kernel<<<1, 256>>>(dl, dw, pw, Ws0, Wn0, Ws1, Wn1);
    gather_kernel<<<M0 / 8, 256>>>(x, nodes, nbr1, nbr2);
    gemm0_kernel<<<152, 512, SMEM_SZ>>>(b0);
    buildA1_kernel<<<M1, 128>>>();
    gemm1_kernel<<<M1 / 128, 256>>>(b1);
    final_kernel<<<B_, 64>>>(tb, out);
}

// round 17
// speedup vs baseline: 1.5072x; 1.0205x over previous
#include <cuda_runtime.h>
#include <cuda_bf16.h>
#include <cuda_fp16.h>
#include <cstdint>

// ---------------- problem constants ----------------
constexpr int T_  = 16;
constexpr int N_  = 50000;
constexpr int F_  = 128;
constexpr int B_  = 1024;
constexpr int S0_ = 10;
constexpr int S1_ = 5;
constexpr int H0_ = 128;
constexpr int H1_ = 64;
constexpr int C_  = 10;
constexpr int G_  = 8;
constexpr int K_  = 5;

constexpr int ROWS0 = B_ + B_ * S0_;   // 11264 rows per time step
constexpr int M0    = T_ * ROWS0;      // 180224
constexpr int M1    = T_ * B_;         // 16384
constexpr int KD    = 256;             // concat K dim [self | neigh]
constexpr int NTILES = M0 / 128;       // 1408
constexpr int TILE_BYTES = 131072;     // per tile: [ph0 hi 32K][ph0 lo 32K][ph1 hi 32K][ph1 lo 32K]

constexpr float FIX_MARGIN = 8e-5f;

// ---------------- device scratch ----------------
__device__ __nv_bfloat16 g_spk0[(size_t)M0 * H0_];  // layer-0 spikes, bf16 0/1 (46 MB)
__device__ __align__(16) char g_A0[(size_t)NTILES * TILE_BYTES]; // fp16 hi/lo swizzled A (184 MB)
__device__ float g_A1[(size_t)M1 * KD];
__device__ float g_spk1[(size_t)M1 * H1_];
__device__ float g_W1[KD * H1_];
__device__ float g_M[T_ * H1_ * C_];
__device__ __align__(16) char g_W0img[2][32768];             // fp16 W hi per k-phase
__device__ float g_W0catT[H0_ * KD];                         // fp32 W, n-major (fixup)
__device__ float g_Ecol[H0_];                                // certified band per column

// ================= helpers =================
__device__ __forceinline__ uint32_t smem_u32(const void* p) {
    uint32_t a;
    asm("{ .reg .u64 t; cvta.to.shared.u64 t, %1; cvt.u32.u64 %0, t; }" : "=r"(a) : "l"(p));
    return a;
}
__device__ __forceinline__ void ldsm_x4(uint32_t* r, uint32_t addr) {
    asm volatile("ldmatrix.sync.aligned.m8n8.x4.shared.b16 {%0,%1,%2,%3}, [%4];"
        : "=r"(r[0]), "=r"(r[1]), "=r"(r[2]), "=r"(r[3]) : "r"(addr));
}
__device__ __forceinline__ void ldsm_x4_t(uint32_t* r, uint32_t addr) {
    asm volatile("ldmatrix.sync.aligned.m8n8.x4.trans.shared.b16 {%0,%1,%2,%3}, [%4];"
        : "=r"(r[0]), "=r"(r[1]), "=r"(r[2]), "=r"(r[3]) : "r"(addr));
}
__device__ __forceinline__ void mma16816(float* d, const uint32_t* a, const uint32_t* b) {
    asm volatile("mma.sync.aligned.m16n8k16.row.col.f32.f16.f16.f32 "
        "{%0,%1,%2,%3}, {%4,%5,%6,%7}, {%8,%9}, {%0,%1,%2,%3};"
        : "+f"(d[0]), "+f"(d[1]), "+f"(d[2]), "+f"(d[3])
        : "r"(a[0]), "r"(a[1]), "r"(a[2]), "r"(a[3]), "r"(b[0]), "r"(b[1]));
}
__device__ __forceinline__ void cp_async16(uint32_t smem_dst, const void* gmem_src) {
    asm volatile("cp.async.cg.shared.global [%0], [%1], 16;"
        :: "r"(smem_dst), "l"(gmem_src) : "memory");
}
#define CP_COMMIT() asm volatile("cp.async.commit_group;" ::: "memory")
#define CP_WAIT1()  asm volatile("cp.async.wait_group 1;" ::: "memory")

// W image: row = k (0..127), 128 n fp16 => 256B/row, XOR-swizzled 16B chunks
__device__ __forceinline__ uint32_t wimg_off(int k, int n) {
    uint32_t chunk = (uint32_t)(n >> 3) ^ (uint32_t)(k & 7);
    return (uint32_t)(k * 256 + (chunk << 4) + (n & 7) * 2);
}
// per-phase A tile: row (0..127), 128 k fp16 => 256B/row, XOR-swizzled 16B chunks
__device__ __forceinline__ uint32_t atile_off(int row, int kk) {
    uint32_t chunk = (uint32_t)(kk >> 3) ^ (uint32_t)(row & 7);
    return (uint32_t)(row * 256 + (chunk << 4) + (kk & 7) * 2);
}
__device__ __forceinline__ void hsplit2(float a, float b, uint32_t& hi, uint32_t& lo) {
    __half ah = __float2half_rn(a);
    __half bh = __float2half_rn(b);
    __half al = __float2half_rn(a - __half2float(ah));
    __half bl = __float2half_rn(b - __half2float(bh));
    hi = (uint32_t)__half_as_ushort(ah) | ((uint32_t)__half_as_ushort(bh) << 16);
    lo = (uint32_t)__half_as_ushort(al) | ((uint32_t)__half_as_ushort(bl) << 16);
}

// ---------------- prep ----------------
__global__ void prep_kernel(const float* __restrict__ dl, const float* __restrict__ dw,
                            const float* __restrict__ pw,
                            const float* __restrict__ Ws0, const float* __restrict__ Wn0,
                            const float* __restrict__ Ws1, const float* __restrict__ Wn1) {
    int tid = threadIdx.x;  // 256
    for (int i = tid; i < 256 * 128; i += 256) {
        int k = i >> 7, n = i & 127;
        float w = (k < 128) ? Ws0[k * H0_ + n] : Wn0[(k - 128) * H0_ + n];
        __half wh = __float2half_rn(w);
        int ph = k >> 7, kl = k & 127;
        *(__half*)(g_W0img[ph] + wimg_off(kl, n)) = wh;
        g_W0catT[n * KD + k] = w;
    }
    for (int i = tid; i < KD * H1_; i += 256) {
        int k = i / H1_, n = i % H1_;
        g_W1[i] = (k < H0_) ? Ws1[k * H1_ + n] : Wn1[(k - H0_) * H1_ + n];
    }
    __syncthreads();
    // certified per-column bound on dropped Ah*Wl product (A in [0,1))
    if (tid < H0_) {
        int n = tid;
        float e = 0.f;
        for (int k = 0; k < KD; k++) {
            float w = g_W0catT[n * KD + k];
            float wl = w - __half2float(__float2half_rn(w));
            e += fabsf(wl);
        }
        g_Ecol[n] = e + FIX_MARGIN;
    }
    if (tid < H1_) {
        int h = tid, g = h / (H1_ / G_);
        float l0 = dl[g * 3 + 0], l1 = dl[g * 3 + 1], l2 = dl[g * 3 + 2];
        float mx = fmaxf(l0, fmaxf(l1, l2));
        float e0 = expf(l0 - mx), e1 = expf(l1 - mx), e2 = expf(l2 - mx);
        float inv = 1.0f / (e0 + e1 + e2);
        float w[3] = {e0 * inv, e1 * inv, e2 * inv};
        float cw[T_];
        for (int u = 0; u < T_; u++) {
            float a = 0.f;
            for (int k = 0; k < K_; k++) {
                int t = u - k + 2;
                if (t >= 0 && t < T_) a += dw[h * K_ + k];
            }
            cw[u] = a;
        }
        const int D[3] = {1, 3, 5};
        for (int s = 0; s < T_; s++) {
            float coef = 0.f;
            for (int i2 = 0; i2 < 3; i2++) {
                int u = s + D[i2];
                if (u < T_) coef += w[i2] * cw[u];
            }
            for (int c = 0; c < C_; c++)
                g_M[(s * H1_ + h) * C_ + c] = coef * pw[h * C_ + c] * (1.0f / T_);
        }
    }
}

// ---------------- gather: warp-per-row, writes mma-ready fp16 hi/lo tiles ----------------
template <int S>
__device__ __forceinline__ float4 nbr_mean(const float* __restrict__ xt,
                                           const int* __restrict__ nb, int fo) {
    float4 nv = make_float4(0.f, 0.f, 0.f, 0.f);
#pragma unroll
    for (int s = 0; s < S; s++) {
        float4 v = *(const float4*)(xt + (size_t)nb[s] * F_ + fo);
        nv.x += v.x; nv.y += v.y; nv.z += v.z; nv.w += v.w;
    }
    const float invS = 1.0f / (float)S;
    nv.x *= invS; nv.y *= invS; nv.z *= invS; nv.w *= invS;
    return nv;
}

__global__ __launch_bounds__(256) void gather_kernel(
        const float* __restrict__ x, const int* __restrict__ nodes,
        const int* __restrict__ nbr1, const int* __restrict__ nbr2) {
    int wid = threadIdx.x >> 5, l = threadIdx.x & 31;
    int m = blockIdx.x * 8 + wid;          // global row
    int t = m / ROWS0, r = m % ROWS0;
    const float* xt = x + (size_t)t * N_ * F_;
    int fo = l * 4;

    int self;
    float4 nv;
    if (r < B_) {
        self = nodes[r];
        nv = nbr_mean<S0_>(xt, nbr1 + ((size_t)t * B_ + r) * S0_, fo);
    } else {
        int j = r - B_;
        self = nbr1[(size_t)t * B_ * S0_ + j];
        nv = nbr_mean<S1_>(xt, nbr2 + ((size_t)t * B_ * S0_ + j) * S1_, fo);
    }
    float4 sv = *(const float4*)(xt + (size_t)self * F_ + fo);

    char* base = g_A0 + (size_t)(m >> 7) * TILE_BYTES;
    uint32_t off = atile_off(m & 127, fo);
    uint32_t h0, l0, h1, l1;
    hsplit2(sv.x, sv.y, h0, l0);
    hsplit2(sv.z, sv.w, h1, l1);
    *(uint2*)(base + off)         = make_uint2(h0, h1);   // ph0 hi
    *(uint2*)(base + 32768 + off) = make_uint2(l0, l1);   // ph0 lo
    hsplit2(nv.x, nv.y, h0, l0);
    hsplit2(nv.z, nv.w, h1, l1);
    *(uint2*)(base + 65536 + off) = make_uint2(h0, h1);   // ph1 hi
    *(uint2*)(base + 98304 + off) = make_uint2(l0, l1);   // ph1 lo
}

// ---------------- persistent cp.async ring-2 GEMM0, 1024 threads ----------------
constexpr int OFF_A   = 0;        // 2 slots x 64KB (hi 32K + lo 32K each)
constexpr int OFF_W   = 131072;   // 2 phases x 32KB
constexpr int OFF_BIAS= 196608;   // 128 floats
constexpr int OFF_ECOL= 197120;   // 128 floats
constexpr int SMEM_SZ = 197632;

__global__ __launch_bounds__(1024, 1)
void gemm0_kernel(const float* __restrict__ bias) {
    extern __shared__ __align__(1024) char sm[];
    uint32_t smb = smem_u32(sm);
    int tid = threadIdx.x;
    int wid = tid >> 5;          // 0..31
    int l   = tid & 31;

    float* s_bias = (float*)(sm + OFF_BIAS);
    float* s_ecol = (float*)(sm + OFF_ECOL);

    // W images (both phases) + bias/ecol
    {
        const uint4* src = (const uint4*)g_W0img;
        uint4* dst = (uint4*)(sm + OFF_W);
        for (int i = tid; i < 4096; i += 1024) dst[i] = src[i];
        if (tid < 128) { s_bias[tid] = bias[tid]; s_ecol[tid] = g_Ecol[tid]; }
    }

    int G = (int)gridDim.x;
    int ntl = (blockIdx.x < NTILES) ? ((NTILES - 1 - (int)blockIdx.x) / G + 1) : 0;
    int nchunks = 2 * ntl;

    // chunk j -> tile blockIdx.x + (j>>1)*G, phase j&1, slot j&1 (64KB hi+lo)
    auto chunk_src = [&](int j) -> const char* {
        int tile = (int)blockIdx.x + (j >> 1) * G;
        return g_A0 + (size_t)tile * TILE_BYTES + (size_t)(j & 1) * 65536;
    };
    auto issue_chunk = [&](int j) {
        const char* src = chunk_src(j) + tid * 16;
        uint32_t dst = smb + OFF_A + (uint32_t)(j & 1) * 65536 + tid * 16;
#pragma unroll
        for (int i = 0; i < 4; i++) cp_async16(dst + i * 16384, src + i * 16384);
    };
    for (int j = 0; j < 2; j++) {
        if (j < nchunks) issue_chunk(j);
        CP_COMMIT();
    }
    __syncthreads();   // W/bias visible before first mma

    // warp tiling: 8 warps M x 4 warps N; warp = 16 rows x 32 cols
    int wm = wid & 7, wn = wid >> 3;
    int m0 = wm * 16;
    int nb0 = wn * 32;

    int a_row = m0 + (l & 15);
    uint32_t a_rowb = (uint32_t)(a_row * 256);
    int a_sw = a_row & 7;
    int a_cs = l >> 4;
    int b_rowoff = (l & 7) + (l & 8);
    int b_sw = l & 7;
    int b_cs = l >> 4;
    uint32_t b_rowb = (uint32_t)(b_rowoff * 256);

    float acc[4][4];

#pragma unroll 1
    for (int j = 0; j < nchunks; j++) {
        int ph = j & 1;
        int tile = (int)blockIdx.x + (j >> 1) * G;
        uint32_t aH = smb + OFF_A + (uint32_t)ph * 65536;
        uint32_t aL = aH + 32768;
        uint32_t wB = smb + OFF_W + (uint32_t)ph * 32768;

        CP_WAIT1();          // chunk j arrived (thread-local)
        __syncthreads();     // visible to all

        if (ph == 0) {
#pragma unroll
            for (int b = 0; b < 4; b++)
#pragma unroll
                for (int c = 0; c < 4; c++) acc[b][c] = 0.f;
        }

#pragma unroll
        for (int ks = 0; ks < 8; ks++) {
            int chunk0 = ks * 2 + a_cs;
            uint32_t offc = (uint32_t)((chunk0 ^ a_sw) << 4);
            uint32_t ah[4], al[4];
            ldsm_x4(ah, aH + a_rowb + offc);
            ldsm_x4(al, aL + a_rowb + offc);
            uint32_t wrow = b_rowb + (uint32_t)(ks * 4096);
#pragma unroll
            for (int n2 = 0; n2 < 2; n2++) {
                int chunkb = (nb0 >> 3) + n2 * 2 + b_cs;
                uint32_t offb = (uint32_t)((chunkb ^ b_sw) << 4);
                uint32_t bh[4];
                ldsm_x4_t(bh, wB + wrow + offb);
                mma16816(acc[n2 * 2 + 0], ah, bh + 0);
                mma16816(acc[n2 * 2 + 1], ah, bh + 2);
                mma16816(acc[n2 * 2 + 0], al, bh + 0);
                mma16816(acc[n2 * 2 + 1], al, bh + 2);
            }
        }

        if (ph == 1) {
            // ---- epilogue: +bias, threshold, flag borderline, write bf16 0/1 ----
            size_t mblk = (size_t)tile * 128;
            int r_in = l >> 2;
            int c2 = (l & 3) * 2;
            const uint32_t ONE = 0x3F80u;
            uint32_t flags = 0u;
            size_t grow0 = mblk + m0 + r_in;
#pragma unroll
            for (int nt = 0; nt < 4; nt++) {
                int col = nb0 + nt * 8 + c2;
                float bb0 = s_bias[col], bb1 = s_bias[col + 1];
                float e0 = s_ecol[col], e1 = s_ecol[col + 1];
                float v00 = acc[nt][0] + bb0;
                float v01 = acc[nt][1] + bb1;
                float v10 = acc[nt][2] + bb0;
                float v11 = acc[nt][3] + bb1;
                uint32_t u0 = ((v00 >= 1.0f) ? ONE : 0u) | (((v01 >= 1.0f) ? ONE : 0u) << 16);
                uint32_t u1 = ((v10 >= 1.0f) ? ONE : 0u) | (((v11 >= 1.0f) ? ONE : 0u) << 16);
                *(uint32_t*)((char*)g_spk0 + (grow0 * H0_ + col) * 2) = u0;
                *(uint32_t*)((char*)g_spk0 + ((grow0 + 8) * H0_ + col) * 2) = u1;
                int slotb = nt * 4;
                if (fabsf(v00 - 1.0f) < e0) flags |= 1u << (slotb + 0);
                if (fabsf(v01 - 1.0f) < e1) flags |= 1u << (slotb + 1);
                if (fabsf(v10 - 1.0f) < e0) flags |= 1u << (slotb + 2);
                if (fabsf(v11 - 1.0f) < e1) flags |= 1u << (slotb + 3);
            }
            // ---- warp-coop certified fixup: fp32 recompute from g_A0 hi+lo (L2-hot) ----
            const char* abase = g_A0 + (size_t)tile * TILE_BYTES;
            int ph_l = l >> 4;             // lane's k-phase
            int kl = (l & 15) * 8;         // lane's k within phase (8 k's)
#pragma unroll 1
            for (int slot = 0; slot < 16; slot++) {
                uint32_t bit = (flags >> slot) & 1u;
                uint32_t ball = __ballot_sync(0xFFFFFFFFu, bit);
                while (ball) {
                    int src = __ffs(ball) - 1;
                    ball &= ball - 1;
                    int nt = slot >> 2, e = slot & 3;
                    int row = m0 + (src >> 2) + ((e & 2) ? 8 : 0);
                    int col = nb0 + nt * 8 + (src & 3) * 2 + (e & 1);
                    const char* ab = abase + ph_l * 65536 + atile_off(row, kl);
                    uint4 hp = *(const uint4*)ab;
                    uint4 lp = *(const uint4*)(ab + 32768);
                    const float* wc = g_W0catT + col * KD + ph_l * 128 + kl;
                    float4 w0 = *(const float4*)(wc);
                    float4 w1 = *(const float4*)(wc + 4);
                    float s = 0.f;
                    __half2 h2, l2;
                    h2 = *(__half2*)&hp.x; l2 = *(__half2*)&lp.x;
                    s = fmaf(__half2float(h2.x) + __half2float(l2.x), w0.x, s);
                    s = fmaf(__half2float(h2.y) + __half2float(l2.y), w0.y, s);
                    h2 = *(__half2*)&hp.y; l2 = *(__half2*)&lp.y;
                    s = fmaf(__half2float(h2.x) + __half2float(l2.x), w0.z, s);
                    s = fmaf(__half2float(h2.y) + __half2float(l2.y), w0.w, s);
                    h2 = *(__half2*)&hp.z; l2 = *(__half2*)&lp.z;
                    s = fmaf(__half2float(h2.x) + __half2float(l2.x), w1.x, s);
                    s = fmaf(__half2float(h2.y) + __half2float(l2.y), w1.y, s);
                    h2 = *(__half2*)&hp.w; l2 = *(__half2*)&lp.w;
                    s = fmaf(__half2float(h2.x) + __half2float(l2.x), w1.z, s);
                    s = fmaf(__half2float(h2.y) + __half2float(l2.y), w1.w, s);
#pragma unroll
                    for (int off = 16; off > 0; off >>= 1)
                        s += __shfl_xor_sync(0xFFFFFFFFu, s, off);
                    if (l == 0) {
                        float v = s + s_bias[col];
                        g_spk0[(mblk + row) * H0_ + col] =
                            (v >= 1.0f) ? __ushort_as_bfloat16((unsigned short)0x3F80u)
                                        : __ushort_as_bfloat16((unsigned short)0);
                    }
                }
            }
        }

        __syncthreads();   // all warps done reading slot before overwrite
        if (j + 2 < nchunks) issue_chunk(j + 2);
        CP_COMMIT();       // unconditional: uniform pending-group count
    }
}

// ---------------- A1 = [spk_self | mean_{S0}(spk_nb)] ----------------
__global__ void buildA1_kernel() {
    int gid = blockIdx.x;
    int t = gid / B_, b = gid % B_;
    int h = threadIdx.x;
    size_t base = (size_t)t * ROWS0;
    float s_self = __bfloat162float(g_spk0[(base + b) * H0_ + h]);
    float acc = 0.f;
#pragma unroll
    for (int s = 0; s < S0_; s++)
        acc += __bfloat162float(g_spk0[(base + B_ + (size_t)b * S0_ + s) * H0_ + h]);
    float* dst = g_A1 + (size_t)gid * KD;
    dst[h] = s_self;
    dst[H0_ + h] = acc * (1.0f / S0_);
}

// ---------------- fp32 FFMA GEMM1 + spike ----------------
__global__ __launch_bounds__(256) void gemm1_kernel(const float* __restrict__ bias) {
    constexpr int BM = 128, BK = 32, TM = 8, BN = 64, TN = 4;
    __shared__ float As[BK][BM + 4];
    __shared__ float Bs[BK][BN];
    int tid = threadIdx.x;
    int tx = tid & 15, ty = tid >> 4;
    size_t mb = (size_t)blockIdx.x * BM;
    float acc[TM][TN];
#pragma unroll
    for (int i = 0; i < TM; i++)
#pragma unroll
        for (int j = 0; j < TN; j++) acc[i][j] = 0.f;
    int a_r = tid >> 3, a_c = (tid & 7) << 2;
    int b_r = tid / 16, b_c = (tid % 16) * 4;
    for (int k0 = 0; k0 < KD; k0 += BK) {
#pragma unroll
        for (int p = 0; p < 4; p++) {
            int row = a_r + p * 32;
            float4 v = *(const float4*)(g_A1 + (mb + row) * KD + k0 + a_c);
            As[a_c + 0][row] = v.x; As[a_c + 1][row] = v.y;
            As[a_c + 2][row] = v.z; As[a_c + 3][row] = v.w;
        }
#pragma unroll
        for (int p = 0; p < 2; p++) {
            int row = b_r + p * 16;
            *(float4*)(&Bs[row][b_c]) = *(const float4*)(g_W1 + (size_t)(k0 + row) * BN + b_c);
        }
        __syncthreads();
#pragma unroll
        for (int kk = 0; kk < BK; kk++) {
            float a[TM], b[TN];
#pragma unroll
            for (int i = 0; i < TM; i++) a[i] = As[kk][ty * TM + i];
#pragma unroll
            for (int j = 0; j < TN; j++) b[j] = Bs[kk][tx * TN + j];
#pragma unroll
            for (int i = 0; i < TM; i++)
#pragma unroll
                for (int j = 0; j < TN; j++) acc[i][j] = fmaf(a[i], b[j], acc[i][j]);
        }
        __syncthreads();
    }
#pragma unroll
    for (int i = 0; i < TM; i++) {
        size_t m = mb + ty * TM + i;
        float4 v;
        v.x = (acc[i][0] + bias[tx * TN + 0] >= 1.0f) ? 1.0f : 0.0f;
        v.y = (acc[i][1] + bias[tx * TN + 1] >= 1.0f) ? 1.0f : 0.0f;
        v.z = (acc[i][2] + bias[tx * TN + 2] >= 1.0f) ? 1.0f : 0.0f;
        v.w = (acc[i][3] + bias[tx * TN + 3] >= 1.0f) ? 1.0f : 0.0f;
        *(float4*)(g_spk1 + m * BN + tx * TN) = v;
    }
}

// ---------------- final contraction ----------------
__global__ void final_kernel(const float* __restrict__ tb, float* __restrict__ out) {
    __shared__ float red[H1_][C_];
    int b = blockIdx.x, h = threadIdx.x;
    float acc[C_];
#pragma unroll
    for (int c = 0; c < C_; c++) acc[c] = 0.f;
    for (int t = 0; t < T_; t++) {
        float s = g_spk1[((size_t)t * B_ + b) * H1_ + h];
        const float* m = g_M + (t * H1_ + h) * C_;
#pragma unroll
        for (int c = 0; c < C_; c++) acc[c] = fmaf(s, m[c], acc[c]);
    }
#pragma unroll
    for (int c = 0; c < C_; c++) red[h][c] = acc[c];
    __syncthreads();
    if (h < C_) {
        float s = tb[h];
        for (int r = 0; r < H1_; r++) s += red[r][h];
        out[b * C_ + h] = s;
    }
}

// ---------------- launch ----------------
extern "C" void kernel_launch(void* const* d_in, const int* in_sizes, int n_in,
                              void* d_out, int out_size) {
    const float* x    = (const float*)d_in[0];
    const int*   nodes= (const int*)d_in[1];
    const int*   nbr1 = (const int*)d_in[2];
    const int*   nbr2 = (const int*)d_in[3];
    const float* Ws0  = (const float*)d_in[4];
    const float* Wn0  = (const float*)d_in[5];
    const float* b0   = (const float*)d_in[6];
    const float* Ws1  = (const float*)d_in[7];
    const float* Wn1  = (const float*)d_in[8];
    const float* b1   = (const float*)d_in[9];
    const float* dl   = (const float*)d_in[10];
    const float* dw   = (const float*)d_in[11];
    const float* pw   = (const float*)d_in[12];
    const float* tb   = (const float*)d_in[13];
    float* out = (float*)d_out;

    static bool init_done = false;
    if (!init_done) {
        cudaFuncSetAttribute(gemm0_kernel,
                             cudaFuncAttributeMaxDynamicSharedMemorySize, SMEM_SZ);
        init_done = true;
    }

    prep_kernel<<<1, 256>>>(dl, dw, pw, Ws0, Wn0, Ws1, Wn1);
    gather_kernel<<<M0 / 8, 256>>>(x, nodes, nbr1, nbr2);
    gemm0_kernel<<<152, 1024, SMEM_SZ>>>(b0);
    buildA1_kernel<<<M1, 128>>>();
    gemm1_kernel<<<M1 / 128, 256>>>(b1);
    final_kernel<<<B_, 64>>>(tb, out);
}